// round 1
// baseline (speedup 1.0000x reference)
#include <cuda_runtime.h>
#include <math.h>

#define NN 20000
#define NE 320000
#define FD 64
#define NH 4
#define HF 256    // NH*FD
#define NGR 64
#define LATD 512
#define GCOLS 832  // FD*(1+3*NH)

// ---------------- scratch (static device globals; no allocs) ----------------
__device__ float g_n0[NN * FD];
__device__ float g_n1[NN * HF];
__device__ float g_n2[NN * HF];
__device__ float g_n3[NN * HF];
__device__ float g_h [NN * HF];
__device__ float g_s [NN * NH];
__device__ float g_d [NN * NH];
__device__ int   g_deg[NN + 1];
__device__ int   g_off[NN + 1];
__device__ int   g_cur[NN];
__device__ int   g_csr[NE];
__device__ int   g_gstart[NGR + 1];
__device__ float g_g[NGR * GCOLS];
__device__ float g_lat[NGR * LATD];

__device__ __forceinline__ float leaky(float x) { return x > 0.f ? x : 0.2f * x; }

// ---------------- node feature encoder: n0 = relu(sf@sW^T+sb)*sm + relu(bf@bW^T+bb)*bm
__global__ void k_encode(const float* __restrict__ sf, const float* __restrict__ bfeat,
                         const float* __restrict__ sm, const float* __restrict__ bm,
                         const float* __restrict__ sW, const float* __restrict__ sb,
                         const float* __restrict__ bW, const float* __restrict__ bb) {
    int node = blockIdx.x;
    int f = threadIdx.x;  // 0..63
    __shared__ float xs[128];
    __shared__ float xb[5];
    for (int i = threadIdx.x; i < 128; i += 64) xs[i] = sf[node * 128 + i];
    if (threadIdx.x < 5) xb[threadIdx.x] = bfeat[node * 5 + threadIdx.x];
    __syncthreads();
    float accS = sb[f], accB = bb[f];
    #pragma unroll 8
    for (int i = 0; i < 128; i++) accS += xs[i] * sW[f * 128 + i];
    #pragma unroll
    for (int i = 0; i < 5; i++) accB += xb[i] * bW[f * 5 + i];
    accS = fmaxf(accS, 0.f);
    accB = fmaxf(accB, 0.f);
    g_n0[node * FD + f] = accS * sm[node] + accB * bm[node];
}

// ---------------- CSR build ----------------
__global__ void k_zero_deg() {
    int i = blockIdx.x * 256 + threadIdx.x;
    if (i <= NN) g_deg[i] = 0;
}

__global__ void k_hist(const int* __restrict__ ei, int E) {
    int i = blockIdx.x * 256 + threadIdx.x;
    if (i < E) atomicAdd(&g_deg[ei[E + i]], 1);
}

__global__ void k_scan() {
    __shared__ int wsum[32];
    __shared__ int carry_s;
    int tid = threadIdx.x, lane = tid & 31, w = tid >> 5;
    if (tid == 0) carry_s = 0;
    __syncthreads();
    for (int base = 0; base < NN; base += 1024) {
        int i = base + tid;
        int v = (i < NN) ? g_deg[i] : 0;
        int x = v;
        #pragma unroll
        for (int o = 1; o < 32; o <<= 1) {
            int y = __shfl_up_sync(0xffffffffu, x, o);
            if (lane >= o) x += y;
        }
        if (lane == 31) wsum[w] = x;
        __syncthreads();
        if (w == 0) {
            int t = wsum[lane];
            #pragma unroll
            for (int o = 1; o < 32; o <<= 1) {
                int y = __shfl_up_sync(0xffffffffu, t, o);
                if (lane >= o) t += y;
            }
            wsum[lane] = t;
        }
        __syncthreads();
        int excl = x - v + (w > 0 ? wsum[w - 1] : 0) + carry_s;
        if (i < NN) { g_off[i] = excl; g_cur[i] = excl; }
        int btotal = wsum[31];
        __syncthreads();
        if (tid == 0) carry_s += btotal;
        __syncthreads();
    }
    if (tid == 0) g_off[NN] = carry_s;
}

__global__ void k_scatter(const int* __restrict__ ei, int E) {
    int i = blockIdx.x * 256 + threadIdx.x;
    if (i < E) {
        int dd = ei[E + i];
        int p = atomicAdd(&g_cur[dd], 1);
        g_csr[p] = ei[i];
    }
}

__global__ void k_gbounds(const int* __restrict__ batch) {
    int i = blockIdx.x * 256 + threadIdx.x;
    if (i == 0) { g_gstart[0] = 0; g_gstart[NGR] = NN; }
    if (i > 0 && i < NN && batch[i] != batch[i - 1]) g_gstart[batch[i]] = i;
}

// ---------------- GEMM: g_h[M,256] = A[M,K] @ W[256,K]^T  (fp32, 128x64x16 tile)
__global__ void k_gemm(const float* __restrict__ A, const float* __restrict__ W, int Kdim) {
    __shared__ float As[16][132];
    __shared__ float Bs[16][68];
    int tid = threadIdx.x;  // 256
    int bm = blockIdx.x * 128, bn = blockIdx.y * 64;
    int tx = tid & 15, ty = tid >> 4;
    float acc[8][4];
    #pragma unroll
    for (int i = 0; i < 8; i++)
        #pragma unroll
        for (int j = 0; j < 4; j++) acc[i][j] = 0.f;

    for (int k0 = 0; k0 < Kdim; k0 += 16) {
        #pragma unroll
        for (int l = 0; l < 2; l++) {
            int idx = tid + l * 256;           // float4 index
            int r = idx >> 2, c4 = idx & 3;
            int row = bm + r;
            float4 v = make_float4(0.f, 0.f, 0.f, 0.f);
            if (row < NN) v = *(const float4*)(A + (size_t)row * Kdim + k0 + c4 * 4);
            As[c4 * 4 + 0][r] = v.x; As[c4 * 4 + 1][r] = v.y;
            As[c4 * 4 + 2][r] = v.z; As[c4 * 4 + 3][r] = v.w;
        }
        {
            int r = tid >> 2, c4 = tid & 3;
            float4 v = *(const float4*)(W + (size_t)(bn + r) * Kdim + k0 + c4 * 4);
            Bs[c4 * 4 + 0][r] = v.x; Bs[c4 * 4 + 1][r] = v.y;
            Bs[c4 * 4 + 2][r] = v.z; Bs[c4 * 4 + 3][r] = v.w;
        }
        __syncthreads();
        #pragma unroll
        for (int k = 0; k < 16; k++) {
            float4 a0 = *(const float4*)&As[k][ty * 8];
            float4 a1 = *(const float4*)&As[k][ty * 8 + 4];
            float4 b0 = *(const float4*)&Bs[k][tx * 4];
            float a[8] = {a0.x, a0.y, a0.z, a0.w, a1.x, a1.y, a1.z, a1.w};
            float b[4] = {b0.x, b0.y, b0.z, b0.w};
            #pragma unroll
            for (int i = 0; i < 8; i++)
                #pragma unroll
                for (int j = 0; j < 4; j++) acc[i][j] += a[i] * b[j];
        }
        __syncthreads();
    }
    #pragma unroll
    for (int i = 0; i < 8; i++) {
        int row = bm + ty * 8 + i;
        if (row < NN) {
            float4 v = make_float4(acc[i][0], acc[i][1], acc[i][2], acc[i][3]);
            *(float4*)(g_h + (size_t)row * HF + bn + tx * 4) = v;
        }
    }
}

// ---------------- per-node attention logits: s[n,h]=<h[n,h,:],a_src[h,:]>, d likewise
__global__ void k_sd(const float* __restrict__ a_src, const float* __restrict__ a_dst) {
    int node = blockIdx.x * 4 + (threadIdx.x >> 5);
    int lane = threadIdx.x & 31;
    if (node >= NN) return;
    const float4* hr = (const float4*)(g_h + (size_t)node * HF);
    const float4* as = (const float4*)a_src;
    const float4* ad = (const float4*)a_dst;
    float4 v1 = hr[lane * 2], v2 = hr[lane * 2 + 1];
    float4 a1 = as[lane * 2], a2 = as[lane * 2 + 1];
    float4 d1 = ad[lane * 2], d2 = ad[lane * 2 + 1];
    float ss = v1.x * a1.x + v1.y * a1.y + v1.z * a1.z + v1.w * a1.w
             + v2.x * a2.x + v2.y * a2.y + v2.z * a2.z + v2.w * a2.w;
    float dd = v1.x * d1.x + v1.y * d1.y + v1.z * d1.z + v1.w * d1.w
             + v2.x * d2.x + v2.y * d2.y + v2.z * d2.z + v2.w * d2.w;
    #pragma unroll
    for (int o = 4; o; o >>= 1) {
        ss += __shfl_down_sync(0xffffffffu, ss, o);
        dd += __shfl_down_sync(0xffffffffu, dd, o);
    }
    if ((lane & 7) == 0) {
        g_s[node * NH + lane / 8] = ss;
        g_d[node * NH + lane / 8] = dd;
    }
}

// ---------------- GAT aggregation: warp per (dst, head); softmax over in-edges + self loop
__global__ void k_agg(const float* __restrict__ bias, float* __restrict__ xout) {
    int warp = threadIdx.x >> 5, lane = threadIdx.x & 31;
    int dst = blockIdx.x * 2 + (warp >> 2);
    int hd = warp & 3;
    int e0 = g_off[dst], e1 = g_off[dst + 1];
    float dd = g_d[dst * NH + hd];

    // pass 1: max over e = leaky(s[src]+d[dst]); self loop included
    float m = leaky(g_s[dst * NH + hd] + dd);
    for (int e = e0 + lane; e < e1; e += 32) {
        int src = g_csr[e];
        m = fmaxf(m, leaky(g_s[src * NH + hd] + dd));
    }
    #pragma unroll
    for (int o = 16; o; o >>= 1) m = fmaxf(m, __shfl_xor_sync(0xffffffffu, m, o));

    // pass 2: weighted accumulate (all lanes carry identical den; lanes split the 64 feats)
    float den, acc0, acc1;
    {
        float w = expf(leaky(g_s[dst * NH + hd] + dd) - m);
        den = w;
        const float2* hr = (const float2*)(g_h + (size_t)dst * HF + hd * FD);
        float2 v = hr[lane];
        acc0 = w * v.x; acc1 = w * v.y;
    }
    for (int e = e0; e < e1; e++) {
        int src = g_csr[e];
        float w = expf(leaky(g_s[src * NH + hd] + dd) - m);
        den += w;
        const float2* hr = (const float2*)(g_h + (size_t)src * HF + hd * FD);
        float2 v = hr[lane];
        acc0 += w * v.x; acc1 += w * v.y;
    }
    float inv = 1.f / den;
    int c = hd * FD + lane * 2;
    float o0 = fmaxf(acc0 * inv + bias[c], 0.f);
    float o1 = fmaxf(acc1 * inv + bias[c + 1], 0.f);
    *(float2*)(xout + (size_t)dst * HF + c) = make_float2(o0, o1);
}

// ---------------- per-graph max pool (batch is sorted; boundaries precomputed)
__global__ void k_pool(const float* __restrict__ x, int C, int gcol0) {
    int gi = blockIdx.x;
    int col = blockIdx.y * 64 + threadIdx.x;
    int i0 = g_gstart[gi], i1 = g_gstart[gi + 1];
    float m = -3.0e38f;
    for (int i = i0; i < i1; i++) m = fmaxf(m, x[(size_t)i * C + col]);
    g_g[gi * GCOLS + gcol0 + col] = m;
}

// ---------------- head MLPs ----------------
__global__ void k_latent(const float* __restrict__ W, const float* __restrict__ b) {
    int gi = blockIdx.x;
    int warp = threadIdx.x >> 5, lane = threadIdx.x & 31;
    int j = blockIdx.y * 8 + warp;
    __shared__ float gs[GCOLS];
    for (int i = threadIdx.x; i < GCOLS; i += 256) gs[i] = g_g[gi * GCOLS + i];
    __syncthreads();
    float acc = 0.f;
    for (int k = lane; k < GCOLS; k += 32) acc += gs[k] * W[(size_t)j * GCOLS + k];
    #pragma unroll
    for (int o = 16; o; o >>= 1) acc += __shfl_xor_sync(0xffffffffu, acc, o);
    if (lane == 0) g_lat[gi * LATD + j] = acc + b[j];
}

__global__ void k_head(const float* __restrict__ muW, const float* __restrict__ mub,
                       const float* __restrict__ vW, const float* __restrict__ vb,
                       float* __restrict__ out) {
    int gi = blockIdx.x;
    int warp = threadIdx.x >> 5, lane = threadIdx.x & 31;
    int j = blockIdx.y * 8 + warp;
    __shared__ float ls[LATD];
    for (int i = threadIdx.x; i < LATD; i += 256) ls[i] = g_lat[gi * LATD + i];
    __syncthreads();
    float am = 0.f, av = 0.f;
    for (int k = lane; k < LATD; k += 32) {
        float l = ls[k];
        am += l * muW[(size_t)j * LATD + k];
        av += l * vW[(size_t)j * LATD + k];
    }
    #pragma unroll
    for (int o = 16; o; o >>= 1) {
        am += __shfl_xor_sync(0xffffffffu, am, o);
        av += __shfl_xor_sync(0xffffffffu, av, o);
    }
    if (lane == 0) {
        out[gi * LATD + j] = am + mub[j];
        out[NGR * LATD + gi * LATD + j] = av + vb[j];
    }
}

// ---------------- launch ----------------
extern "C" void kernel_launch(void* const* d_in, const int* in_sizes, int n_in,
                              void* d_out, int out_size) {
    const float* street  = (const float*)d_in[0];
    const float* build   = (const float*)d_in[1];
    const float* smask   = (const float*)d_in[2];
    const float* bmask   = (const float*)d_in[3];
    const int*   ei      = (const int*)d_in[4];
    const int*   batch   = (const int*)d_in[5];
    const float* sW      = (const float*)d_in[6];
    const float* sb      = (const float*)d_in[7];
    const float* bW      = (const float*)d_in[8];
    const float* bb      = (const float*)d_in[9];
    const float* W1      = (const float*)d_in[10];
    const float* as1     = (const float*)d_in[11];
    const float* ad1     = (const float*)d_in[12];
    const float* b1      = (const float*)d_in[13];
    const float* W2      = (const float*)d_in[14];
    const float* as2     = (const float*)d_in[15];
    const float* ad2     = (const float*)d_in[16];
    const float* b2      = (const float*)d_in[17];
    const float* W3      = (const float*)d_in[18];
    const float* as3     = (const float*)d_in[19];
    const float* ad3     = (const float*)d_in[20];
    const float* b3      = (const float*)d_in[21];
    const float* aggW    = (const float*)d_in[22];
    const float* aggb    = (const float*)d_in[23];
    const float* muW     = (const float*)d_in[24];
    const float* mub     = (const float*)d_in[25];
    const float* varW    = (const float*)d_in[26];
    const float* varb    = (const float*)d_in[27];
    float* out = (float*)d_out;

    int E = in_sizes[4] / 2;

    float *n0, *n1, *n2, *n3;
    cudaGetSymbolAddress((void**)&n0, g_n0);
    cudaGetSymbolAddress((void**)&n1, g_n1);
    cudaGetSymbolAddress((void**)&n2, g_n2);
    cudaGetSymbolAddress((void**)&n3, g_n3);

    // node encoding + CSR build + graph boundaries
    k_zero_deg<<<(NN + 256) / 256 + 1, 256>>>();
    k_encode<<<NN, 64>>>(street, build, smask, bmask, sW, sb, bW, bb);
    k_hist<<<(E + 255) / 256, 256>>>(ei, E);
    k_scan<<<1, 1024>>>();
    k_scatter<<<(E + 255) / 256, 256>>>(ei, E);
    k_gbounds<<<(NN + 255) / 256, 256>>>(batch);

    dim3 ggrid((NN + 127) / 128, 4);

    // layer 1
    k_gemm<<<ggrid, 256>>>(n0, W1, FD);
    k_sd<<<(NN + 3) / 4, 128>>>(as1, ad1);
    k_agg<<<NN / 2, 256>>>(b1, n1);
    // layer 2
    k_gemm<<<ggrid, 256>>>(n1, W2, HF);
    k_sd<<<(NN + 3) / 4, 128>>>(as2, ad2);
    k_agg<<<NN / 2, 256>>>(b2, n2);
    // layer 3
    k_gemm<<<ggrid, 256>>>(n2, W3, HF);
    k_sd<<<(NN + 3) / 4, 128>>>(as3, ad3);
    k_agg<<<NN / 2, 256>>>(b3, n3);

    // pooling
    k_pool<<<dim3(NGR, 1), 64>>>(n0, FD, 0);
    k_pool<<<dim3(NGR, 4), 64>>>(n1, HF, FD);
    k_pool<<<dim3(NGR, 4), 64>>>(n2, HF, FD + HF);
    k_pool<<<dim3(NGR, 4), 64>>>(n3, HF, FD + 2 * HF);

    // head
    k_latent<<<dim3(NGR, LATD / 8), 256>>>(aggW, aggb);
    k_head<<<dim3(NGR, LATD / 8), 256>>>(muW, mub, varW, varb, out);
}

// round 2
// speedup vs baseline: 1.0175x; 1.0175x over previous
#include <cuda_runtime.h>
#include <math.h>

#define NN 20000
#define NE 320000
#define FD 64
#define NH 4
#define HF 256    // NH*FD
#define NGR 64
#define LATD 512
#define GCOLS 832  // FD*(1+3*NH)
#define NBLK ((NN + 255) / 256)   // 79 scan blocks

// ---------------- scratch (static device globals; no allocs) ----------------
__device__ float g_n0[NN * FD];
__device__ float g_n1[NN * HF];
__device__ float g_n2[NN * HF];
__device__ float g_n3[NN * HF];
__device__ float g_h [NN * HF];
__device__ float g_s [NN * NH];
__device__ float g_d [NN * NH];
__device__ int   g_deg[NN + 1];
__device__ int   g_off[NN + 1];
__device__ int   g_cur[NN];
__device__ int   g_csr[NE];
__device__ int   g_bsum[NBLK + 1];
__device__ int   g_gstart[NGR + 1];
__device__ float g_g[NGR * GCOLS];
__device__ float g_lat[NGR * LATD];

__device__ __forceinline__ float leaky(float x) { return x > 0.f ? x : 0.2f * x; }

// ---------------- node feature encoder ----------------
__global__ void k_encode(const float* __restrict__ sf, const float* __restrict__ bfeat,
                         const float* __restrict__ sm, const float* __restrict__ bm,
                         const float* __restrict__ sW, const float* __restrict__ sb,
                         const float* __restrict__ bW, const float* __restrict__ bb) {
    int node = blockIdx.x;
    int f = threadIdx.x;  // 0..63
    __shared__ float xs[128];
    __shared__ float xb[5];
    for (int i = threadIdx.x; i < 128; i += 64) xs[i] = sf[node * 128 + i];
    if (threadIdx.x < 5) xb[threadIdx.x] = bfeat[node * 5 + threadIdx.x];
    __syncthreads();
    float a0 = 0.f, a1 = 0.f, a2 = 0.f, a3 = 0.f;
    const float* wr = sW + f * 128;
    #pragma unroll 8
    for (int i = 0; i < 128; i += 4) {
        a0 += xs[i + 0] * wr[i + 0];
        a1 += xs[i + 1] * wr[i + 1];
        a2 += xs[i + 2] * wr[i + 2];
        a3 += xs[i + 3] * wr[i + 3];
    }
    float accS = (a0 + a1) + (a2 + a3) + sb[f];
    float accB = bb[f];
    #pragma unroll
    for (int i = 0; i < 5; i++) accB += xb[i] * bW[f * 5 + i];
    accS = fmaxf(accS, 0.f);
    accB = fmaxf(accB, 0.f);
    g_n0[node * FD + f] = accS * sm[node] + accB * bm[node];
}

// ---------------- CSR build ----------------
__global__ void k_zero_deg() {
    int i = blockIdx.x * 256 + threadIdx.x;
    if (i <= NN) g_deg[i] = 0;
}

__global__ void k_hist(const int* __restrict__ ei, int E) {
    int i = blockIdx.x * 256 + threadIdx.x;
    if (i < E) atomicAdd(&g_deg[ei[E + i]], 1);
}

// decoupled 3-phase scan
__global__ void k_scan1() {
    __shared__ int wsum[8];
    int b = blockIdx.x, tid = threadIdx.x, lane = tid & 31, w = tid >> 5;
    int i = b * 256 + tid;
    int v = (i < NN) ? g_deg[i] : 0;
    int x = v;
    #pragma unroll
    for (int o = 1; o < 32; o <<= 1) {
        int y = __shfl_up_sync(0xffffffffu, x, o);
        if (lane >= o) x += y;
    }
    if (lane == 31) wsum[w] = x;
    __syncthreads();
    if (tid < 8) {
        int t = wsum[tid];
        #pragma unroll
        for (int o = 1; o < 8; o <<= 1) {
            int y = __shfl_up_sync(0xffu, t, o);
            if (tid >= o) t += y;
        }
        wsum[tid] = t;
    }
    __syncthreads();
    int excl = x - v + (w > 0 ? wsum[w - 1] : 0);
    if (i < NN) g_off[i] = excl;
    if (tid == 255) g_bsum[b] = excl + v;
}

__global__ void k_scan2(int nb) {
    int lane = threadIdx.x;
    int carry = 0;
    for (int base = 0; base < nb; base += 32) {
        int i = base + lane;
        int v = (i < nb) ? g_bsum[i] : 0;
        int x = v;
        #pragma unroll
        for (int o = 1; o < 32; o <<= 1) {
            int y = __shfl_up_sync(0xffffffffu, x, o);
            if (lane >= o) x += y;
        }
        if (i < nb) g_bsum[i] = x - v + carry;
        carry += __shfl_sync(0xffffffffu, x, 31);
    }
}

__global__ void k_scan3(int E) {
    int i = blockIdx.x * 256 + threadIdx.x;
    if (i < NN) {
        int o = g_off[i] + g_bsum[blockIdx.x];
        g_off[i] = o;
        g_cur[i] = o;
    }
    if (i == 0) g_off[NN] = E;
}

__global__ void k_scatter(const int* __restrict__ ei, int E) {
    int i = blockIdx.x * 256 + threadIdx.x;
    if (i < E) {
        int dd = ei[E + i];
        int p = atomicAdd(&g_cur[dd], 1);
        g_csr[p] = ei[i];
    }
}

__global__ void k_gbounds(const int* __restrict__ batch) {
    int i = blockIdx.x * 256 + threadIdx.x;
    if (i == 0) { g_gstart[0] = 0; g_gstart[NGR] = NN; }
    if (i > 0 && i < NN && batch[i] != batch[i - 1]) g_gstart[batch[i]] = i;
}

// ---------------- GEMM: g_h[M,256] = A[M,K] @ W[256,K]^T
// 128x128x16 tile, 256 threads, 8x8 microtile, double-buffered smem
__global__ void __launch_bounds__(256, 2) k_gemm(const float* __restrict__ A,
                                                 const float* __restrict__ W, int Kdim) {
    __shared__ float As[2][16][136];
    __shared__ float Bs[2][16][136];
    int tid = threadIdx.x;
    int bm = blockIdx.x * 128, bn = blockIdx.y * 128;
    int tx = tid & 15, ty = tid >> 4;   // col group 0..15, row group 0..15

    float acc[8][8];
    #pragma unroll
    for (int i = 0; i < 8; i++)
        #pragma unroll
        for (int j = 0; j < 8; j++) acc[i][j] = 0.f;

    // load indices for a 128x16 tile: 512 float4, 2 per thread
    int l0 = tid * 2, l1 = tid * 2 + 1;
    int r0 = l0 >> 2, c40 = l0 & 3;
    int r1 = l1 >> 2, c41 = l1 & 3;

    int nk = Kdim >> 4;
    float4 pA0, pA1, pB0, pB1;

    // prologue: load k0=0 tile directly to smem buf 0
    {
        int row0 = bm + r0, row1 = bm + r1;
        float4 v0 = make_float4(0.f, 0.f, 0.f, 0.f), v1 = v0;
        if (row0 < NN) v0 = *(const float4*)(A + (size_t)row0 * Kdim + c40 * 4);
        if (row1 < NN) v1 = *(const float4*)(A + (size_t)row1 * Kdim + c41 * 4);
        As[0][c40 * 4 + 0][r0] = v0.x; As[0][c40 * 4 + 1][r0] = v0.y;
        As[0][c40 * 4 + 2][r0] = v0.z; As[0][c40 * 4 + 3][r0] = v0.w;
        As[0][c41 * 4 + 0][r1] = v1.x; As[0][c41 * 4 + 1][r1] = v1.y;
        As[0][c41 * 4 + 2][r1] = v1.z; As[0][c41 * 4 + 3][r1] = v1.w;
        float4 w0 = *(const float4*)(W + (size_t)(bn + r0) * Kdim + c40 * 4);
        float4 w1 = *(const float4*)(W + (size_t)(bn + r1) * Kdim + c41 * 4);
        Bs[0][c40 * 4 + 0][r0] = w0.x; Bs[0][c40 * 4 + 1][r0] = w0.y;
        Bs[0][c40 * 4 + 2][r0] = w0.z; Bs[0][c40 * 4 + 3][r0] = w0.w;
        Bs[0][c41 * 4 + 0][r1] = w1.x; Bs[0][c41 * 4 + 1][r1] = w1.y;
        Bs[0][c41 * 4 + 2][r1] = w1.z; Bs[0][c41 * 4 + 3][r1] = w1.w;
    }
    __syncthreads();

    int buf = 0;
    for (int k0 = 0; k0 < nk; k0++) {
        // prefetch next tile into regs
        if (k0 + 1 < nk) {
            int kb = (k0 + 1) * 16;
            int row0 = bm + r0, row1 = bm + r1;
            pA0 = make_float4(0.f, 0.f, 0.f, 0.f); pA1 = pA0;
            if (row0 < NN) pA0 = *(const float4*)(A + (size_t)row0 * Kdim + kb + c40 * 4);
            if (row1 < NN) pA1 = *(const float4*)(A + (size_t)row1 * Kdim + kb + c41 * 4);
            pB0 = *(const float4*)(W + (size_t)(bn + r0) * Kdim + kb + c40 * 4);
            pB1 = *(const float4*)(W + (size_t)(bn + r1) * Kdim + kb + c41 * 4);
        }
        // compute on current buffer
        #pragma unroll
        for (int k = 0; k < 16; k++) {
            float4 a0 = *(const float4*)&As[buf][k][ty * 8];
            float4 a1 = *(const float4*)&As[buf][k][ty * 8 + 4];
            float4 b0 = *(const float4*)&Bs[buf][k][tx * 8];
            float4 b1 = *(const float4*)&Bs[buf][k][tx * 8 + 4];
            float a[8] = {a0.x, a0.y, a0.z, a0.w, a1.x, a1.y, a1.z, a1.w};
            float b[8] = {b0.x, b0.y, b0.z, b0.w, b1.x, b1.y, b1.z, b1.w};
            #pragma unroll
            for (int i = 0; i < 8; i++)
                #pragma unroll
                for (int j = 0; j < 8; j++) acc[i][j] += a[i] * b[j];
        }
        // store prefetched regs into other buffer
        if (k0 + 1 < nk) {
            int nb2 = buf ^ 1;
            As[nb2][c40 * 4 + 0][r0] = pA0.x; As[nb2][c40 * 4 + 1][r0] = pA0.y;
            As[nb2][c40 * 4 + 2][r0] = pA0.z; As[nb2][c40 * 4 + 3][r0] = pA0.w;
            As[nb2][c41 * 4 + 0][r1] = pA1.x; As[nb2][c41 * 4 + 1][r1] = pA1.y;
            As[nb2][c41 * 4 + 2][r1] = pA1.z; As[nb2][c41 * 4 + 3][r1] = pA1.w;
            Bs[nb2][c40 * 4 + 0][r0] = pB0.x; Bs[nb2][c40 * 4 + 1][r0] = pB0.y;
            Bs[nb2][c40 * 4 + 2][r0] = pB0.z; Bs[nb2][c40 * 4 + 3][r0] = pB0.w;
            Bs[nb2][c41 * 4 + 0][r1] = pB1.x; Bs[nb2][c41 * 4 + 1][r1] = pB1.y;
            Bs[nb2][c41 * 4 + 2][r1] = pB1.z; Bs[nb2][c41 * 4 + 3][r1] = pB1.w;
        }
        __syncthreads();
        buf ^= 1;
    }

    #pragma unroll
    for (int i = 0; i < 8; i++) {
        int row = bm + ty * 8 + i;
        if (row < NN) {
            float4 v0 = make_float4(acc[i][0], acc[i][1], acc[i][2], acc[i][3]);
            float4 v1 = make_float4(acc[i][4], acc[i][5], acc[i][6], acc[i][7]);
            *(float4*)(g_h + (size_t)row * HF + bn + tx * 8) = v0;
            *(float4*)(g_h + (size_t)row * HF + bn + tx * 8 + 4) = v1;
        }
    }
}

// ---------------- per-node attention logits ----------------
__global__ void k_sd(const float* __restrict__ a_src, const float* __restrict__ a_dst) {
    int node = blockIdx.x * 4 + (threadIdx.x >> 5);
    int lane = threadIdx.x & 31;
    if (node >= NN) return;
    const float4* hr = (const float4*)(g_h + (size_t)node * HF);
    const float4* as = (const float4*)a_src;
    const float4* ad = (const float4*)a_dst;
    float4 v1 = hr[lane * 2], v2 = hr[lane * 2 + 1];
    float4 a1 = as[lane * 2], a2 = as[lane * 2 + 1];
    float4 d1 = ad[lane * 2], d2 = ad[lane * 2 + 1];
    float ss = v1.x * a1.x + v1.y * a1.y + v1.z * a1.z + v1.w * a1.w
             + v2.x * a2.x + v2.y * a2.y + v2.z * a2.z + v2.w * a2.w;
    float dd = v1.x * d1.x + v1.y * d1.y + v1.z * d1.z + v1.w * d1.w
             + v2.x * d2.x + v2.y * d2.y + v2.z * d2.z + v2.w * d2.w;
    #pragma unroll
    for (int o = 4; o; o >>= 1) {
        ss += __shfl_down_sync(0xffffffffu, ss, o);
        dd += __shfl_down_sync(0xffffffffu, dd, o);
    }
    if ((lane & 7) == 0) {
        g_s[node * NH + lane / 8] = ss;
        g_d[node * NH + lane / 8] = dd;
    }
}

// ---------------- GAT aggregation: warp per (dst, head) ----------------
__global__ void k_agg(const float* __restrict__ bias, float* __restrict__ xout) {
    int warp = threadIdx.x >> 5, lane = threadIdx.x & 31;
    int dst = blockIdx.x * 2 + (warp >> 2);
    int hd = warp & 3;
    int e0 = g_off[dst], e1 = g_off[dst + 1];
    float dd = g_d[dst * NH + hd];
    float sself = g_s[dst * NH + hd];

    // pass 1: max (lane-parallel over edges) — self loop included
    float m = leaky(sself + dd);
    for (int e = e0 + lane; e < e1; e += 32) {
        int src = g_csr[e];
        m = fmaxf(m, leaky(g_s[src * NH + hd] + dd));
    }
    #pragma unroll
    for (int o = 16; o; o >>= 1) m = fmaxf(m, __shfl_xor_sync(0xffffffffu, m, o));

    // pass 2: weighted feature accumulate (lanes split 64 feats)
    float den, acc0, acc1;
    {
        float w = expf(leaky(sself + dd) - m);
        den = w;
        const float2* hr = (const float2*)(g_h + (size_t)dst * HF + hd * FD);
        float2 v = hr[lane];
        acc0 = w * v.x; acc1 = w * v.y;
    }
    for (int e = e0; e < e1; e++) {
        int src = g_csr[e];
        float w = expf(leaky(g_s[src * NH + hd] + dd) - m);
        den += w;
        const float2* hr = (const float2*)(g_h + (size_t)src * HF + hd * FD);
        float2 v = hr[lane];
        acc0 += w * v.x; acc1 += w * v.y;
    }
    float inv = 1.f / den;
    int c = hd * FD + lane * 2;
    float o0 = fmaxf(acc0 * inv + bias[c], 0.f);
    float o1 = fmaxf(acc1 * inv + bias[c + 1], 0.f);
    *(float2*)(xout + (size_t)dst * HF + c) = make_float2(o0, o1);
}

// ---------------- per-graph max pool (4-way row split + smem reduce) ----------------
__global__ void k_pool(const float* __restrict__ x, int C, int gcol0) {
    __shared__ float red[4][64];
    int gi = blockIdx.x;
    int col = blockIdx.y * 64 + (threadIdx.x & 63);
    int rg = threadIdx.x >> 6;   // 0..3
    int i0 = g_gstart[gi], i1 = g_gstart[gi + 1];
    float m = -3.0e38f;
    for (int i = i0 + rg; i < i1; i += 4) m = fmaxf(m, x[(size_t)i * C + col]);
    red[rg][threadIdx.x & 63] = m;
    __syncthreads();
    if (rg == 0) {
        m = fmaxf(fmaxf(red[0][col & 63], red[1][col & 63]),
                  fmaxf(red[2][col & 63], red[3][col & 63]));
        g_g[gi * GCOLS + gcol0 + col] = m;
    }
}

// ---------------- head MLPs ----------------
__global__ void k_latent(const float* __restrict__ W, const float* __restrict__ b) {
    int gi = blockIdx.x;
    int warp = threadIdx.x >> 5, lane = threadIdx.x & 31;
    int j = blockIdx.y * 8 + warp;
    __shared__ float gs[GCOLS];
    for (int i = threadIdx.x; i < GCOLS; i += 256) gs[i] = g_g[gi * GCOLS + i];
    __syncthreads();
    float acc = 0.f;
    for (int k = lane; k < GCOLS; k += 32) acc += gs[k] * W[(size_t)j * GCOLS + k];
    #pragma unroll
    for (int o = 16; o; o >>= 1) acc += __shfl_xor_sync(0xffffffffu, acc, o);
    if (lane == 0) g_lat[gi * LATD + j] = acc + b[j];
}

__global__ void k_head(const float* __restrict__ muW, const float* __restrict__ mub,
                       const float* __restrict__ vW, const float* __restrict__ vb,
                       float* __restrict__ out) {
    int gi = blockIdx.x;
    int warp = threadIdx.x >> 5, lane = threadIdx.x & 31;
    int j = blockIdx.y * 8 + warp;
    __shared__ float ls[LATD];
    for (int i = threadIdx.x; i < LATD; i += 256) ls[i] = g_lat[gi * LATD + i];
    __syncthreads();
    float am = 0.f, av = 0.f;
    for (int k = lane; k < LATD; k += 32) {
        float l = ls[k];
        am += l * muW[(size_t)j * LATD + k];
        av += l * vW[(size_t)j * LATD + k];
    }
    #pragma unroll
    for (int o = 16; o; o >>= 1) {
        am += __shfl_xor_sync(0xffffffffu, am, o);
        av += __shfl_xor_sync(0xffffffffu, av, o);
    }
    if (lane == 0) {
        out[gi * LATD + j] = am + mub[j];
        out[NGR * LATD + gi * LATD + j] = av + vb[j];
    }
}

// ---------------- launch ----------------
extern "C" void kernel_launch(void* const* d_in, const int* in_sizes, int n_in,
                              void* d_out, int out_size) {
    const float* street  = (const float*)d_in[0];
    const float* build   = (const float*)d_in[1];
    const float* smask   = (const float*)d_in[2];
    const float* bmask   = (const float*)d_in[3];
    const int*   ei      = (const int*)d_in[4];
    const int*   batch   = (const int*)d_in[5];
    const float* sW      = (const float*)d_in[6];
    const float* sb      = (const float*)d_in[7];
    const float* bW      = (const float*)d_in[8];
    const float* bb      = (const float*)d_in[9];
    const float* W1      = (const float*)d_in[10];
    const float* as1     = (const float*)d_in[11];
    const float* ad1     = (const float*)d_in[12];
    const float* b1      = (const float*)d_in[13];
    const float* W2      = (const float*)d_in[14];
    const float* as2     = (const float*)d_in[15];
    const float* ad2     = (const float*)d_in[16];
    const float* b2      = (const float*)d_in[17];
    const float* W3      = (const float*)d_in[18];
    const float* as3     = (const float*)d_in[19];
    const float* ad3     = (const float*)d_in[20];
    const float* b3      = (const float*)d_in[21];
    const float* aggW    = (const float*)d_in[22];
    const float* aggb    = (const float*)d_in[23];
    const float* muW     = (const float*)d_in[24];
    const float* mub     = (const float*)d_in[25];
    const float* varW    = (const float*)d_in[26];
    const float* varb    = (const float*)d_in[27];
    float* out = (float*)d_out;

    int E = in_sizes[4] / 2;

    float *n0, *n1, *n2, *n3;
    cudaGetSymbolAddress((void**)&n0, g_n0);
    cudaGetSymbolAddress((void**)&n1, g_n1);
    cudaGetSymbolAddress((void**)&n2, g_n2);
    cudaGetSymbolAddress((void**)&n3, g_n3);

    // node encoding + CSR build + graph boundaries
    k_zero_deg<<<(NN + 256) / 256 + 1, 256>>>();
    k_encode<<<NN, 64>>>(street, build, smask, bmask, sW, sb, bW, bb);
    k_hist<<<(E + 255) / 256, 256>>>(ei, E);
    k_scan1<<<NBLK, 256>>>();
    k_scan2<<<1, 32>>>(NBLK);
    k_scan3<<<NBLK, 256>>>(E);
    k_scatter<<<(E + 255) / 256, 256>>>(ei, E);
    k_gbounds<<<(NN + 255) / 256, 256>>>(batch);

    dim3 ggrid((NN + 127) / 128, 2);

    // layer 1
    k_gemm<<<ggrid, 256>>>(n0, W1, FD);
    k_sd<<<(NN + 3) / 4, 128>>>(as1, ad1);
    k_agg<<<NN / 2, 256>>>(b1, n1);
    // layer 2
    k_gemm<<<ggrid, 256>>>(n1, W2, HF);
    k_sd<<<(NN + 3) / 4, 128>>>(as2, ad2);
    k_agg<<<NN / 2, 256>>>(b2, n2);
    // layer 3
    k_gemm<<<ggrid, 256>>>(n2, W3, HF);
    k_sd<<<(NN + 3) / 4, 128>>>(as3, ad3);
    k_agg<<<NN / 2, 256>>>(b3, n3);

    // pooling
    k_pool<<<dim3(NGR, 1), 256>>>(n0, FD, 0);
    k_pool<<<dim3(NGR, 4), 256>>>(n1, HF, FD);
    k_pool<<<dim3(NGR, 4), 256>>>(n2, HF, FD + HF);
    k_pool<<<dim3(NGR, 4), 256>>>(n3, HF, FD + 2 * HF);

    // head
    k_latent<<<dim3(NGR, LATD / 8), 256>>>(aggW, aggb);
    k_head<<<dim3(NGR, LATD / 8), 256>>>(muW, mub, varW, varb, out);
}

// round 3
// speedup vs baseline: 1.1736x; 1.1534x over previous
#include <cuda_runtime.h>
#include <math.h>

#define NN 20000
#define NE 320000
#define FD 64
#define NH 4
#define HF 256    // NH*FD
#define NGR 64
#define LATD 512
#define GCOLS 832  // FD*(1+3*NH)
#define NBLK ((NN + 255) / 256)   // scan blocks

// ---------------- scratch (static device globals; no allocs) ----------------
__device__ float g_n0[NN * FD];
__device__ float g_n1[NN * HF];
__device__ float g_n2[NN * HF];
__device__ float g_n3[NN * HF];
__device__ float g_h [NN * HF];
__device__ float g_s [NN * NH];
__device__ float g_d [NN * NH];
__device__ int   g_deg[NN + 1];
__device__ int   g_off[NN + 1];
__device__ int   g_cur[NN];
__device__ int   g_csr[NE];
__device__ int   g_bsum[NBLK + 1];
__device__ int   g_gstart[NGR + 1];
__device__ float g_g[NGR * GCOLS];
__device__ float g_lat[NGR * LATD];

__device__ __forceinline__ float leaky(float x) { return x > 0.f ? x : 0.2f * x; }

__device__ __forceinline__ unsigned f2tf32(float x) {
    unsigned r;
    asm("cvt.rna.tf32.f32 %0, %1;" : "=r"(r) : "f"(x));
    return r;
}

// ---------------- node feature encoder ----------------
__global__ void k_encode(const float* __restrict__ sf, const float* __restrict__ bfeat,
                         const float* __restrict__ sm, const float* __restrict__ bm,
                         const float* __restrict__ sW, const float* __restrict__ sb,
                         const float* __restrict__ bW, const float* __restrict__ bb) {
    int node = blockIdx.x;
    int f = threadIdx.x;  // 0..63
    __shared__ float xs[128];
    __shared__ float xb[5];
    for (int i = threadIdx.x; i < 128; i += 64) xs[i] = sf[node * 128 + i];
    if (threadIdx.x < 5) xb[threadIdx.x] = bfeat[node * 5 + threadIdx.x];
    __syncthreads();
    float a0 = 0.f, a1 = 0.f, a2 = 0.f, a3 = 0.f;
    const float* wr = sW + f * 128;
    #pragma unroll 8
    for (int i = 0; i < 128; i += 4) {
        a0 += xs[i + 0] * wr[i + 0];
        a1 += xs[i + 1] * wr[i + 1];
        a2 += xs[i + 2] * wr[i + 2];
        a3 += xs[i + 3] * wr[i + 3];
    }
    float accS = (a0 + a1) + (a2 + a3) + sb[f];
    float accB = bb[f];
    #pragma unroll
    for (int i = 0; i < 5; i++) accB += xb[i] * bW[f * 5 + i];
    accS = fmaxf(accS, 0.f);
    accB = fmaxf(accB, 0.f);
    g_n0[node * FD + f] = accS * sm[node] + accB * bm[node];
}

// ---------------- CSR build ----------------
__global__ void k_zero_deg() {
    int i = blockIdx.x * 256 + threadIdx.x;
    if (i <= NN) g_deg[i] = 0;
}

__global__ void k_hist(const int* __restrict__ ei, int E) {
    int i = blockIdx.x * 256 + threadIdx.x;
    if (i < E) atomicAdd(&g_deg[ei[E + i]], 1);
}

__global__ void k_scan1() {
    __shared__ int wsum[8];
    int b = blockIdx.x, tid = threadIdx.x, lane = tid & 31, w = tid >> 5;
    int i = b * 256 + tid;
    int v = (i < NN) ? g_deg[i] : 0;
    int x = v;
    #pragma unroll
    for (int o = 1; o < 32; o <<= 1) {
        int y = __shfl_up_sync(0xffffffffu, x, o);
        if (lane >= o) x += y;
    }
    if (lane == 31) wsum[w] = x;
    __syncthreads();
    if (tid < 8) {
        int t = wsum[tid];
        #pragma unroll
        for (int o = 1; o < 8; o <<= 1) {
            int y = __shfl_up_sync(0xffu, t, o);
            if (tid >= o) t += y;
        }
        wsum[tid] = t;
    }
    __syncthreads();
    int excl = x - v + (w > 0 ? wsum[w - 1] : 0);
    if (i < NN) g_off[i] = excl;
    if (tid == 255) g_bsum[b] = excl + v;
}

__global__ void k_scan2(int nb) {
    int lane = threadIdx.x;
    int carry = 0;
    for (int base = 0; base < nb; base += 32) {
        int i = base + lane;
        int v = (i < nb) ? g_bsum[i] : 0;
        int x = v;
        #pragma unroll
        for (int o = 1; o < 32; o <<= 1) {
            int y = __shfl_up_sync(0xffffffffu, x, o);
            if (lane >= o) x += y;
        }
        if (i < nb) g_bsum[i] = x - v + carry;
        carry += __shfl_sync(0xffffffffu, x, 31);
    }
}

__global__ void k_scan3(int E) {
    int i = blockIdx.x * 256 + threadIdx.x;
    if (i < NN) {
        int o = g_off[i] + g_bsum[blockIdx.x];
        g_off[i] = o;
        g_cur[i] = o;
    }
    if (i == 0) g_off[NN] = E;
}

__global__ void k_scatter(const int* __restrict__ ei, int E) {
    int i = blockIdx.x * 256 + threadIdx.x;
    if (i < E) {
        int dd = ei[E + i];
        int p = atomicAdd(&g_cur[dd], 1);
        g_csr[p] = ei[i];
    }
}

__global__ void k_gbounds(const int* __restrict__ batch) {
    int i = blockIdx.x * 256 + threadIdx.x;
    if (i == 0) { g_gstart[0] = 0; g_gstart[NGR] = NN; }
    if (i > 0 && i < NN && batch[i] != batch[i - 1]) g_gstart[batch[i]] = i;
}

// ---------------- tf32 tensor-core GEMM: g_h[M,256] = A[M,K] @ W[256,K]^T
// 128x128xBK32 tile, 256 thr (8 warps as 4x2), warp tile 32x64 via m16n8k8 mma
__global__ void __launch_bounds__(256, 2) k_gemm(const float* __restrict__ A,
                                                 const float* __restrict__ W, int Kdim) {
    __shared__ unsigned As[128][40];   // [row][k]  (pad 40 -> conflict-free frag loads)
    __shared__ unsigned Bs[32][136];   // [k][n]    (pad 136 -> conflict-free frag loads)
    int tid = threadIdx.x;
    int lane = tid & 31, warp = tid >> 5;
    int warpM = warp >> 1, warpN = warp & 1;
    int bm = blockIdx.x * 128, bn = blockIdx.y * 128;
    int gid = lane >> 2, tig = lane & 3;   // mma group id / thread-in-group

    float acc[2][8][4];
    #pragma unroll
    for (int mt = 0; mt < 2; mt++)
        #pragma unroll
        for (int nt = 0; nt < 8; nt++)
            #pragma unroll
            for (int j = 0; j < 4; j++) acc[mt][nt][j] = 0.f;

    for (int k0 = 0; k0 < Kdim; k0 += 32) {
        // stage A: 128 rows x 32 k  (1024 float4, 4 per thread)
        #pragma unroll
        for (int l = 0; l < 4; l++) {
            int f = tid + 256 * l;
            int row = f >> 3, k4 = f & 7;
            float4 v = make_float4(0.f, 0.f, 0.f, 0.f);
            int gr = bm + row;
            if (gr < NN) v = *(const float4*)(A + (size_t)gr * Kdim + k0 + k4 * 4);
            uint4 u = make_uint4(f2tf32(v.x), f2tf32(v.y), f2tf32(v.z), f2tf32(v.w));
            *(uint4*)&As[row][k4 * 4] = u;
        }
        // stage B: W[bn+n][k] -> Bs[k][n]
        #pragma unroll
        for (int l = 0; l < 4; l++) {
            int f = tid + 256 * l;
            int n = f >> 3, k4 = f & 7;
            float4 v = *(const float4*)(W + (size_t)(bn + n) * Kdim + k0 + k4 * 4);
            Bs[k4 * 4 + 0][n] = f2tf32(v.x);
            Bs[k4 * 4 + 1][n] = f2tf32(v.y);
            Bs[k4 * 4 + 2][n] = f2tf32(v.z);
            Bs[k4 * 4 + 3][n] = f2tf32(v.w);
        }
        __syncthreads();

        #pragma unroll
        for (int k8 = 0; k8 < 4; k8++) {
            unsigned a[2][4];
            #pragma unroll
            for (int mt = 0; mt < 2; mt++) {
                int row = warpM * 32 + mt * 16 + gid;
                int col = k8 * 8 + tig;
                a[mt][0] = As[row][col];
                a[mt][1] = As[row + 8][col];
                a[mt][2] = As[row][col + 4];
                a[mt][3] = As[row + 8][col + 4];
            }
            #pragma unroll
            for (int nt = 0; nt < 8; nt++) {
                int colB = warpN * 64 + nt * 8 + gid;
                int rowB = k8 * 8 + tig;
                unsigned b0 = Bs[rowB][colB];
                unsigned b1 = Bs[rowB + 4][colB];
                #pragma unroll
                for (int mt = 0; mt < 2; mt++) {
                    asm volatile(
                        "mma.sync.aligned.m16n8k8.row.col.f32.tf32.tf32.f32 "
                        "{%0,%1,%2,%3}, {%4,%5,%6,%7}, {%8,%9}, {%0,%1,%2,%3};"
                        : "+f"(acc[mt][nt][0]), "+f"(acc[mt][nt][1]),
                          "+f"(acc[mt][nt][2]), "+f"(acc[mt][nt][3])
                        : "r"(a[mt][0]), "r"(a[mt][1]), "r"(a[mt][2]), "r"(a[mt][3]),
                          "r"(b0), "r"(b1));
                }
            }
        }
        __syncthreads();
    }

    // epilogue
    #pragma unroll
    for (int mt = 0; mt < 2; mt++) {
        int row0 = bm + warpM * 32 + mt * 16 + gid;
        #pragma unroll
        for (int nt = 0; nt < 8; nt++) {
            int col = bn + warpN * 64 + nt * 8 + tig * 2;
            if (row0 < NN)
                *(float2*)(g_h + (size_t)row0 * HF + col) =
                    make_float2(acc[mt][nt][0], acc[mt][nt][1]);
            if (row0 + 8 < NN)
                *(float2*)(g_h + (size_t)(row0 + 8) * HF + col) =
                    make_float2(acc[mt][nt][2], acc[mt][nt][3]);
        }
    }
}

// ---------------- per-node attention logits ----------------
__global__ void k_sd(const float* __restrict__ a_src, const float* __restrict__ a_dst) {
    int node = blockIdx.x * 4 + (threadIdx.x >> 5);
    int lane = threadIdx.x & 31;
    if (node >= NN) return;
    const float4* hr = (const float4*)(g_h + (size_t)node * HF);
    const float4* as = (const float4*)a_src;
    const float4* ad = (const float4*)a_dst;
    float4 v1 = hr[lane * 2], v2 = hr[lane * 2 + 1];
    float4 a1 = as[lane * 2], a2 = as[lane * 2 + 1];
    float4 d1 = ad[lane * 2], d2 = ad[lane * 2 + 1];
    float ss = v1.x * a1.x + v1.y * a1.y + v1.z * a1.z + v1.w * a1.w
             + v2.x * a2.x + v2.y * a2.y + v2.z * a2.z + v2.w * a2.w;
    float dd = v1.x * d1.x + v1.y * d1.y + v1.z * d1.z + v1.w * d1.w
             + v2.x * d2.x + v2.y * d2.y + v2.z * d2.z + v2.w * d2.w;
    #pragma unroll
    for (int o = 4; o; o >>= 1) {
        ss += __shfl_down_sync(0xffffffffu, ss, o);
        dd += __shfl_down_sync(0xffffffffu, dd, o);
    }
    if ((lane & 7) == 0) {
        g_s[node * NH + lane / 8] = ss;
        g_d[node * NH + lane / 8] = dd;
    }
}

// ---------------- GAT aggregation: one warp per dst, ALL 4 heads together
// lane l owns features l*8 .. l*8+7  (head = l>>3)
__global__ void k_agg(const float* __restrict__ bias, float* __restrict__ xout) {
    int warp = threadIdx.x >> 5, lane = threadIdx.x & 31;
    int dst = blockIdx.x * 8 + warp;
    if (dst >= NN) return;
    int e0 = g_off[dst], e1 = g_off[dst + 1];
    float4 d4 = *(const float4*)(g_d + dst * NH);
    float4 s4self = *(const float4*)(g_s + dst * NH);

    // pass 1: per-head max (lane-parallel over edges), incl. self loop
    float4 m;
    m.x = leaky(s4self.x + d4.x); m.y = leaky(s4self.y + d4.y);
    m.z = leaky(s4self.z + d4.z); m.w = leaky(s4self.w + d4.w);
    for (int e = e0 + lane; e < e1; e += 32) {
        int src = g_csr[e];
        float4 s4 = *(const float4*)(g_s + src * NH);
        m.x = fmaxf(m.x, leaky(s4.x + d4.x));
        m.y = fmaxf(m.y, leaky(s4.y + d4.y));
        m.z = fmaxf(m.z, leaky(s4.z + d4.z));
        m.w = fmaxf(m.w, leaky(s4.w + d4.w));
    }
    #pragma unroll
    for (int o = 16; o; o >>= 1) {
        m.x = fmaxf(m.x, __shfl_xor_sync(0xffffffffu, m.x, o));
        m.y = fmaxf(m.y, __shfl_xor_sync(0xffffffffu, m.y, o));
        m.z = fmaxf(m.z, __shfl_xor_sync(0xffffffffu, m.z, o));
        m.w = fmaxf(m.w, __shfl_xor_sync(0xffffffffu, m.w, o));
    }

    int hd = lane >> 3;
    float mh = (hd == 0) ? m.x : (hd == 1) ? m.y : (hd == 2) ? m.z : m.w;
    float ddh = (hd == 0) ? d4.x : (hd == 1) ? d4.y : (hd == 2) ? d4.z : d4.w;
    float ssl = (hd == 0) ? s4self.x : (hd == 1) ? s4self.y : (hd == 2) ? s4self.z : s4self.w;

    // pass 2: weighted accumulate; self loop first
    float den, ac[8];
    {
        float w = expf(leaky(ssl + ddh) - mh);
        den = w;
        const float4* hr = (const float4*)(g_h + (size_t)dst * HF) + lane * 2;
        float4 v0 = hr[0], v1 = hr[1];
        ac[0] = w * v0.x; ac[1] = w * v0.y; ac[2] = w * v0.z; ac[3] = w * v0.w;
        ac[4] = w * v1.x; ac[5] = w * v1.y; ac[6] = w * v1.z; ac[7] = w * v1.w;
    }
    for (int e = e0; e < e1; e++) {
        int src = g_csr[e];
        float4 s4 = *(const float4*)(g_s + src * NH);  // broadcast
        float sh = (hd == 0) ? s4.x : (hd == 1) ? s4.y : (hd == 2) ? s4.z : s4.w;
        float w = expf(leaky(sh + ddh) - mh);
        den += w;
        const float4* hr = (const float4*)(g_h + (size_t)src * HF) + lane * 2;
        float4 v0 = hr[0], v1 = hr[1];
        ac[0] += w * v0.x; ac[1] += w * v0.y; ac[2] += w * v0.z; ac[3] += w * v0.w;
        ac[4] += w * v1.x; ac[5] += w * v1.y; ac[6] += w * v1.z; ac[7] += w * v1.w;
    }
    float inv = 1.f / den;
    int c = lane * 8;
    const float4* bp = (const float4*)(bias + c);
    float4 b0 = bp[0], b1 = bp[1];
    float4 o0 = make_float4(fmaxf(ac[0] * inv + b0.x, 0.f), fmaxf(ac[1] * inv + b0.y, 0.f),
                            fmaxf(ac[2] * inv + b0.z, 0.f), fmaxf(ac[3] * inv + b0.w, 0.f));
    float4 o1 = make_float4(fmaxf(ac[4] * inv + b1.x, 0.f), fmaxf(ac[5] * inv + b1.y, 0.f),
                            fmaxf(ac[6] * inv + b1.z, 0.f), fmaxf(ac[7] * inv + b1.w, 0.f));
    float4* op = (float4*)(xout + (size_t)dst * HF + c);
    op[0] = o0; op[1] = o1;
}

// ---------------- per-graph max pool ----------------
__global__ void k_pool(const float* __restrict__ x, int C, int gcol0) {
    __shared__ float red[4][64];
    int gi = blockIdx.x;
    int col = blockIdx.y * 64 + (threadIdx.x & 63);
    int rg = threadIdx.x >> 6;   // 0..3
    int i0 = g_gstart[gi], i1 = g_gstart[gi + 1];
    float m = -3.0e38f;
    for (int i = i0 + rg; i < i1; i += 4) m = fmaxf(m, x[(size_t)i * C + col]);
    red[rg][threadIdx.x & 63] = m;
    __syncthreads();
    if (rg == 0) {
        m = fmaxf(fmaxf(red[0][col & 63], red[1][col & 63]),
                  fmaxf(red[2][col & 63], red[3][col & 63]));
        g_g[gi * GCOLS + gcol0 + col] = m;
    }
}

// ---------------- head MLPs ----------------
__global__ void k_latent(const float* __restrict__ W, const float* __restrict__ b) {
    int gi = blockIdx.x;
    int warp = threadIdx.x >> 5, lane = threadIdx.x & 31;
    int j = blockIdx.y * 8 + warp;
    __shared__ float gs[GCOLS];
    for (int i = threadIdx.x; i < GCOLS; i += 256) gs[i] = g_g[gi * GCOLS + i];
    __syncthreads();
    float acc = 0.f;
    for (int k = lane; k < GCOLS; k += 32) acc += gs[k] * W[(size_t)j * GCOLS + k];
    #pragma unroll
    for (int o = 16; o; o >>= 1) acc += __shfl_xor_sync(0xffffffffu, acc, o);
    if (lane == 0) g_lat[gi * LATD + j] = acc + b[j];
}

__global__ void k_head(const float* __restrict__ muW, const float* __restrict__ mub,
                       const float* __restrict__ vW, const float* __restrict__ vb,
                       float* __restrict__ out) {
    int gi = blockIdx.x;
    int warp = threadIdx.x >> 5, lane = threadIdx.x & 31;
    int j = blockIdx.y * 8 + warp;
    __shared__ float ls[LATD];
    for (int i = threadIdx.x; i < LATD; i += 256) ls[i] = g_lat[gi * LATD + i];
    __syncthreads();
    float am = 0.f, av = 0.f;
    for (int k = lane; k < LATD; k += 32) {
        float l = ls[k];
        am += l * muW[(size_t)j * LATD + k];
        av += l * vW[(size_t)j * LATD + k];
    }
    #pragma unroll
    for (int o = 16; o; o >>= 1) {
        am += __shfl_xor_sync(0xffffffffu, am, o);
        av += __shfl_xor_sync(0xffffffffu, av, o);
    }
    if (lane == 0) {
        out[gi * LATD + j] = am + mub[j];
        out[NGR * LATD + gi * LATD + j] = av + vb[j];
    }
}

// ---------------- launch ----------------
extern "C" void kernel_launch(void* const* d_in, const int* in_sizes, int n_in,
                              void* d_out, int out_size) {
    const float* street  = (const float*)d_in[0];
    const float* build   = (const float*)d_in[1];
    const float* smask   = (const float*)d_in[2];
    const float* bmask   = (const float*)d_in[3];
    const int*   ei      = (const int*)d_in[4];
    const int*   batch   = (const int*)d_in[5];
    const float* sW      = (const float*)d_in[6];
    const float* sb      = (const float*)d_in[7];
    const float* bW      = (const float*)d_in[8];
    const float* bb      = (const float*)d_in[9];
    const float* W1      = (const float*)d_in[10];
    const float* as1     = (const float*)d_in[11];
    const float* ad1     = (const float*)d_in[12];
    const float* b1      = (const float*)d_in[13];
    const float* W2      = (const float*)d_in[14];
    const float* as2     = (const float*)d_in[15];
    const float* ad2     = (const float*)d_in[16];
    const float* b2      = (const float*)d_in[17];
    const float* W3      = (const float*)d_in[18];
    const float* as3     = (const float*)d_in[19];
    const float* ad3     = (const float*)d_in[20];
    const float* b3      = (const float*)d_in[21];
    const float* aggW    = (const float*)d_in[22];
    const float* aggb    = (const float*)d_in[23];
    const float* muW     = (const float*)d_in[24];
    const float* mub     = (const float*)d_in[25];
    const float* varW    = (const float*)d_in[26];
    const float* varb    = (const float*)d_in[27];
    float* out = (float*)d_out;

    int E = in_sizes[4] / 2;

    float *n0, *n1, *n2, *n3;
    cudaGetSymbolAddress((void**)&n0, g_n0);
    cudaGetSymbolAddress((void**)&n1, g_n1);
    cudaGetSymbolAddress((void**)&n2, g_n2);
    cudaGetSymbolAddress((void**)&n3, g_n3);

    k_zero_deg<<<(NN + 256) / 256 + 1, 256>>>();
    k_encode<<<NN, 64>>>(street, build, smask, bmask, sW, sb, bW, bb);
    k_hist<<<(E + 255) / 256, 256>>>(ei, E);
    k_scan1<<<NBLK, 256>>>();
    k_scan2<<<1, 32>>>(NBLK);
    k_scan3<<<NBLK, 256>>>(E);
    k_scatter<<<(E + 255) / 256, 256>>>(ei, E);
    k_gbounds<<<(NN + 255) / 256, 256>>>(batch);

    dim3 ggrid((NN + 127) / 128, 2);

    // layer 1
    k_gemm<<<ggrid, 256>>>(n0, W1, FD);
    k_sd<<<(NN + 3) / 4, 128>>>(as1, ad1);
    k_agg<<<(NN + 7) / 8, 256>>>(b1, n1);
    // layer 2
    k_gemm<<<ggrid, 256>>>(n1, W2, HF);
    k_sd<<<(NN + 3) / 4, 128>>>(as2, ad2);
    k_agg<<<(NN + 7) / 8, 256>>>(b2, n2);
    // layer 3
    k_gemm<<<ggrid, 256>>>(n2, W3, HF);
    k_sd<<<(NN + 3) / 4, 128>>>(as3, ad3);
    k_agg<<<(NN + 7) / 8, 256>>>(b3, n3);

    // pooling
    k_pool<<<dim3(NGR, 1), 256>>>(n0, FD, 0);
    k_pool<<<dim3(NGR, 4), 256>>>(n1, HF, FD);
    k_pool<<<dim3(NGR, 4), 256>>>(n2, HF, FD + HF);
    k_pool<<<dim3(NGR, 4), 256>>>(n3, HF, FD + 2 * HF);

    // head
    k_latent<<<dim3(NGR, LATD / 8), 256>>>(aggW, aggb);
    k_head<<<dim3(NGR, LATD / 8), 256>>>(muW, mub, varW, varb, out);
}

// round 4
// speedup vs baseline: 2.6114x; 2.2251x over previous
#include <cuda_runtime.h>
#include <math.h>

#define NN 20000
#define NE 320000
#define FD 64
#define NH 4
#define HF 256    // NH*FD
#define NGR 64
#define LATD 512
#define GCOLS 832  // FD*(1+3*NH)
#define NBLK ((NN + 255) / 256)   // scan blocks
#define ENB 64    // encode nodes per block

// ---------------- scratch (static device globals; no allocs) ----------------
__device__ float g_n0[NN * FD];
__device__ float g_n1[NN * HF];
__device__ float g_n2[NN * HF];
__device__ float g_n3[NN * HF];
__device__ float g_h [NN * HF];
__device__ float g_s [NN * NH];
__device__ float g_d [NN * NH];
__device__ int   g_deg[NN + 1];
__device__ int   g_off[NN + 1];
__device__ int   g_cur[NN];
__device__ int   g_csr[NE];
__device__ int   g_bsum[NBLK + 1];
__device__ int   g_gstart[NGR + 1];
__device__ float g_g[NGR * GCOLS];
__device__ float g_lat[NGR * LATD];

__device__ __forceinline__ float leaky(float x) { return x > 0.f ? x : 0.2f * x; }

__device__ __forceinline__ unsigned f2tf32(float x) {
    unsigned r;
    asm("cvt.rna.tf32.f32 %0, %1;" : "=r"(r) : "f"(x));
    return r;
}

// ---------------- node feature encoder (weights in smem, 64 nodes/block)
// also zeroes g_deg
__global__ void __launch_bounds__(256) k_encode(
        const float* __restrict__ sf, const float* __restrict__ bfeat,
        const float* __restrict__ sm, const float* __restrict__ bm,
        const float* __restrict__ sW, const float* __restrict__ sb,
        const float* __restrict__ bW, const float* __restrict__ bb) {
    __shared__ float sWs[64 * 132];
    __shared__ float bWs[64 * 5];
    __shared__ float sbs[64], bbs[64];
    __shared__ float xbs[ENB * 5];
    int t = threadIdx.x;
    int node0 = blockIdx.x * ENB;

    int zi = blockIdx.x * 256 + t;
    if (zi <= NN) g_deg[zi] = 0;

    for (int l = t; l < 64 * 32; l += 256) {   // 2048 float4 of sW
        int r = l >> 5, c = l & 31;
        float4 v = *(const float4*)(sW + r * 128 + c * 4);
        *(float4*)&sWs[r * 132 + c * 4] = v;
    }
    if (t < 64) { sbs[t] = sb[t]; bbs[t] = bb[t]; }
    for (int l = t; l < 320; l += 256) bWs[l] = bW[l];
    for (int l = t; l < ENB * 5; l += 256) {
        int n = l / 5, c = l % 5;
        int g = node0 + n;
        xbs[l] = (g < NN) ? bfeat[g * 5 + c] : 0.f;
    }
    __syncthreads();

    int f = t & 63, slot = t >> 6;  // slot uniform within a warp
    float acc[16];
    #pragma unroll
    for (int i = 0; i < 16; i++) acc[i] = 0.f;

    #pragma unroll
    for (int kc = 0; kc < 16; kc++) {
        float4 w0 = *(float4*)&sWs[f * 132 + kc * 8];
        float4 w1 = *(float4*)&sWs[f * 132 + kc * 8 + 4];
        #pragma unroll
        for (int ni = 0; ni < 16; ni++) {
            int g = node0 + slot * 16 + ni;
            int gc = (g < NN) ? g : (NN - 1);
            const float4* xp = (const float4*)(sf + (size_t)gc * 128 + kc * 8);
            float4 x0 = xp[0], x1 = xp[1];
            acc[ni] += w0.x * x0.x + w0.y * x0.y + w0.z * x0.z + w0.w * x0.w
                     + w1.x * x1.x + w1.y * x1.y + w1.z * x1.z + w1.w * x1.w;
        }
    }
    #pragma unroll
    for (int ni = 0; ni < 16; ni++) {
        int n = slot * 16 + ni;
        int g = node0 + n;
        if (g < NN) {
            float accS = fmaxf(acc[ni] + sbs[f], 0.f);
            float accB = bbs[f];
            #pragma unroll
            for (int i = 0; i < 5; i++) accB += xbs[n * 5 + i] * bWs[f * 5 + i];
            accB = fmaxf(accB, 0.f);
            g_n0[(size_t)g * FD + f] = accS * sm[g] + accB * bm[g];
        }
    }
}

// ---------------- CSR build ----------------
__global__ void k_hist(const int* __restrict__ ei, int E) {
    int i = blockIdx.x * 256 + threadIdx.x;
    if (i < E) atomicAdd(&g_deg[ei[E + i]], 1);
}

__global__ void k_scan1() {
    __shared__ int wsum[8];
    int b = blockIdx.x, tid = threadIdx.x, lane = tid & 31, w = tid >> 5;
    int i = b * 256 + tid;
    int v = (i < NN) ? g_deg[i] : 0;
    int x = v;
    #pragma unroll
    for (int o = 1; o < 32; o <<= 1) {
        int y = __shfl_up_sync(0xffffffffu, x, o);
        if (lane >= o) x += y;
    }
    if (lane == 31) wsum[w] = x;
    __syncthreads();
    if (tid < 8) {
        int t2 = wsum[tid];
        #pragma unroll
        for (int o = 1; o < 8; o <<= 1) {
            int y = __shfl_up_sync(0xffu, t2, o);
            if (tid >= o) t2 += y;
        }
        wsum[tid] = t2;
    }
    __syncthreads();
    int excl = x - v + (w > 0 ? wsum[w - 1] : 0);
    if (i < NN) g_off[i] = excl;
    if (tid == 255) g_bsum[b] = excl + v;
}

// scan3: each block computes its own prefix of block sums (79 values, cheap)
__global__ void k_scan3(int E, int nb) {
    __shared__ int pre;
    int b = blockIdx.x, tid = threadIdx.x;
    if (tid < 32) {
        int s = 0;
        for (int j = tid; j < b; j += 32) s += g_bsum[j];
        #pragma unroll
        for (int o = 16; o; o >>= 1) s += __shfl_xor_sync(0xffffffffu, s, o);
        if (tid == 0) pre = s;
    }
    __syncthreads();
    int i = b * 256 + tid;
    if (i < NN) {
        int o = g_off[i] + pre;
        g_off[i] = o;
        g_cur[i] = o;
    }
    if (i == 0) g_off[NN] = E;
}

// scatter + graph-boundary detection fused
__global__ void k_scatter(const int* __restrict__ ei, const int* __restrict__ batch, int E) {
    int i = blockIdx.x * 256 + threadIdx.x;
    if (i < E) {
        int dd = ei[E + i];
        int p = atomicAdd(&g_cur[dd], 1);
        g_csr[p] = ei[i];
    }
    if (i == 0) { g_gstart[0] = 0; g_gstart[NGR] = NN; }
    if (i > 0 && i < NN && batch[i] != batch[i - 1]) g_gstart[batch[i]] = i;
}

// ---------------- tf32 tensor-core GEMM + fused attention logits
// g_h[M,256] = A[M,K] @ W[256,K]^T ; also g_s/g_d per (row, head)
__global__ void __launch_bounds__(256, 2) k_gemm(const float* __restrict__ A,
                                                 const float* __restrict__ W, int Kdim,
                                                 const float* __restrict__ as_,
                                                 const float* __restrict__ ad_) {
    __shared__ unsigned As[128][40];
    __shared__ unsigned Bs[32][136];
    int tid = threadIdx.x;
    int lane = tid & 31, warp = tid >> 5;
    int warpM = warp >> 1, warpN = warp & 1;
    int bm = blockIdx.x * 128, bn = blockIdx.y * 128;
    int gid = lane >> 2, tig = lane & 3;

    float acc[2][8][4];
    #pragma unroll
    for (int mt = 0; mt < 2; mt++)
        #pragma unroll
        for (int nt = 0; nt < 8; nt++)
            #pragma unroll
            for (int j = 0; j < 4; j++) acc[mt][nt][j] = 0.f;

    for (int k0 = 0; k0 < Kdim; k0 += 32) {
        #pragma unroll
        for (int l = 0; l < 4; l++) {
            int fidx = tid + 256 * l;
            int row = fidx >> 3, k4 = fidx & 7;
            float4 v = make_float4(0.f, 0.f, 0.f, 0.f);
            int gr = bm + row;
            if (gr < NN) v = *(const float4*)(A + (size_t)gr * Kdim + k0 + k4 * 4);
            uint4 u = make_uint4(f2tf32(v.x), f2tf32(v.y), f2tf32(v.z), f2tf32(v.w));
            *(uint4*)&As[row][k4 * 4] = u;
        }
        #pragma unroll
        for (int l = 0; l < 4; l++) {
            int fidx = tid + 256 * l;
            int n = fidx >> 3, k4 = fidx & 7;
            float4 v = *(const float4*)(W + (size_t)(bn + n) * Kdim + k0 + k4 * 4);
            Bs[k4 * 4 + 0][n] = f2tf32(v.x);
            Bs[k4 * 4 + 1][n] = f2tf32(v.y);
            Bs[k4 * 4 + 2][n] = f2tf32(v.z);
            Bs[k4 * 4 + 3][n] = f2tf32(v.w);
        }
        __syncthreads();

        #pragma unroll
        for (int k8 = 0; k8 < 4; k8++) {
            unsigned a[2][4];
            #pragma unroll
            for (int mt = 0; mt < 2; mt++) {
                int row = warpM * 32 + mt * 16 + gid;
                int col = k8 * 8 + tig;
                a[mt][0] = As[row][col];
                a[mt][1] = As[row + 8][col];
                a[mt][2] = As[row][col + 4];
                a[mt][3] = As[row + 8][col + 4];
            }
            #pragma unroll
            for (int nt = 0; nt < 8; nt++) {
                int colB = warpN * 64 + nt * 8 + gid;
                int rowB = k8 * 8 + tig;
                unsigned b0 = Bs[rowB][colB];
                unsigned b1 = Bs[rowB + 4][colB];
                #pragma unroll
                for (int mt = 0; mt < 2; mt++) {
                    asm volatile(
                        "mma.sync.aligned.m16n8k8.row.col.f32.tf32.tf32.f32 "
                        "{%0,%1,%2,%3}, {%4,%5,%6,%7}, {%8,%9}, {%0,%1,%2,%3};"
                        : "+f"(acc[mt][nt][0]), "+f"(acc[mt][nt][1]),
                          "+f"(acc[mt][nt][2]), "+f"(acc[mt][nt][3])
                        : "r"(a[mt][0]), "r"(a[mt][1]), "r"(a[mt][2]), "r"(a[mt][3]),
                          "r"(b0), "r"(b1));
                }
            }
        }
        __syncthreads();
    }

    // epilogue: write h + fused s/d logits
    int hd = (bn >> 6) + warpN;   // this warp's head
    #pragma unroll
    for (int mt = 0; mt < 2; mt++) {
        int row0 = bm + warpM * 32 + mt * 16 + gid;
        float sp0 = 0.f, sp8 = 0.f, dp0 = 0.f, dp8 = 0.f;
        #pragma unroll
        for (int nt = 0; nt < 8; nt++) {
            int col = bn + warpN * 64 + nt * 8 + tig * 2;
            int lc = nt * 8 + tig * 2;  // local col within head
            float2 a2s = *(const float2*)(as_ + hd * 64 + lc);
            float2 a2d = *(const float2*)(ad_ + hd * 64 + lc);
            sp0 += acc[mt][nt][0] * a2s.x + acc[mt][nt][1] * a2s.y;
            sp8 += acc[mt][nt][2] * a2s.x + acc[mt][nt][3] * a2s.y;
            dp0 += acc[mt][nt][0] * a2d.x + acc[mt][nt][1] * a2d.y;
            dp8 += acc[mt][nt][2] * a2d.x + acc[mt][nt][3] * a2d.y;
            if (row0 < NN)
                *(float2*)(g_h + (size_t)row0 * HF + col) =
                    make_float2(acc[mt][nt][0], acc[mt][nt][1]);
            if (row0 + 8 < NN)
                *(float2*)(g_h + (size_t)(row0 + 8) * HF + col) =
                    make_float2(acc[mt][nt][2], acc[mt][nt][3]);
        }
        // reduce across tig quad (lanes gid*4 + tig)
        #pragma unroll
        for (int o = 1; o < 4; o <<= 1) {
            sp0 += __shfl_xor_sync(0xffffffffu, sp0, o);
            sp8 += __shfl_xor_sync(0xffffffffu, sp8, o);
            dp0 += __shfl_xor_sync(0xffffffffu, dp0, o);
            dp8 += __shfl_xor_sync(0xffffffffu, dp8, o);
        }
        if (tig == 0) {
            if (row0 < NN)     { g_s[row0 * NH + hd] = sp0; g_d[row0 * NH + hd] = dp0; }
            if (row0 + 8 < NN) { g_s[(row0 + 8) * NH + hd] = sp8; g_d[(row0 + 8) * NH + hd] = dp8; }
        }
    }
}

// ---------------- GAT aggregation: one warp per dst, all 4 heads ----------------
__global__ void k_agg(const float* __restrict__ bias, float* __restrict__ xout) {
    int warp = threadIdx.x >> 5, lane = threadIdx.x & 31;
    int dst = blockIdx.x * 8 + warp;
    if (dst >= NN) return;
    int e0 = g_off[dst], e1 = g_off[dst + 1];
    float4 d4 = *(const float4*)(g_d + dst * NH);
    float4 s4self = *(const float4*)(g_s + dst * NH);

    float4 m;
    m.x = leaky(s4self.x + d4.x); m.y = leaky(s4self.y + d4.y);
    m.z = leaky(s4self.z + d4.z); m.w = leaky(s4self.w + d4.w);
    for (int e = e0 + lane; e < e1; e += 32) {
        int src = g_csr[e];
        float4 s4 = *(const float4*)(g_s + src * NH);
        m.x = fmaxf(m.x, leaky(s4.x + d4.x));
        m.y = fmaxf(m.y, leaky(s4.y + d4.y));
        m.z = fmaxf(m.z, leaky(s4.z + d4.z));
        m.w = fmaxf(m.w, leaky(s4.w + d4.w));
    }
    #pragma unroll
    for (int o = 16; o; o >>= 1) {
        m.x = fmaxf(m.x, __shfl_xor_sync(0xffffffffu, m.x, o));
        m.y = fmaxf(m.y, __shfl_xor_sync(0xffffffffu, m.y, o));
        m.z = fmaxf(m.z, __shfl_xor_sync(0xffffffffu, m.z, o));
        m.w = fmaxf(m.w, __shfl_xor_sync(0xffffffffu, m.w, o));
    }

    int hd = lane >> 3;
    float mh = (hd == 0) ? m.x : (hd == 1) ? m.y : (hd == 2) ? m.z : m.w;
    float ddh = (hd == 0) ? d4.x : (hd == 1) ? d4.y : (hd == 2) ? d4.z : d4.w;
    float ssl = (hd == 0) ? s4self.x : (hd == 1) ? s4self.y : (hd == 2) ? s4self.z : s4self.w;

    float den, ac[8];
    {
        float w = expf(leaky(ssl + ddh) - mh);
        den = w;
        const float4* hr = (const float4*)(g_h + (size_t)dst * HF) + lane * 2;
        float4 v0 = hr[0], v1 = hr[1];
        ac[0] = w * v0.x; ac[1] = w * v0.y; ac[2] = w * v0.z; ac[3] = w * v0.w;
        ac[4] = w * v1.x; ac[5] = w * v1.y; ac[6] = w * v1.z; ac[7] = w * v1.w;
    }
    for (int e = e0; e < e1; e++) {
        int src = g_csr[e];
        float4 s4 = *(const float4*)(g_s + src * NH);
        float sh = (hd == 0) ? s4.x : (hd == 1) ? s4.y : (hd == 2) ? s4.z : s4.w;
        float w = expf(leaky(sh + ddh) - mh);
        den += w;
        const float4* hr = (const float4*)(g_h + (size_t)src * HF) + lane * 2;
        float4 v0 = hr[0], v1 = hr[1];
        ac[0] += w * v0.x; ac[1] += w * v0.y; ac[2] += w * v0.z; ac[3] += w * v0.w;
        ac[4] += w * v1.x; ac[5] += w * v1.y; ac[6] += w * v1.z; ac[7] += w * v1.w;
    }
    float inv = 1.f / den;
    int c = lane * 8;
    const float4* bp = (const float4*)(bias + c);
    float4 b0 = bp[0], b1 = bp[1];
    float4 o0 = make_float4(fmaxf(ac[0] * inv + b0.x, 0.f), fmaxf(ac[1] * inv + b0.y, 0.f),
                            fmaxf(ac[2] * inv + b0.z, 0.f), fmaxf(ac[3] * inv + b0.w, 0.f));
    float4 o1 = make_float4(fmaxf(ac[4] * inv + b1.x, 0.f), fmaxf(ac[5] * inv + b1.y, 0.f),
                            fmaxf(ac[6] * inv + b1.z, 0.f), fmaxf(ac[7] * inv + b1.w, 0.f));
    float4* op = (float4*)(xout + (size_t)dst * HF + c);
    op[0] = o0; op[1] = o1;
}

// ---------------- per-graph max pool ----------------
__global__ void k_pool(const float* __restrict__ x, int C, int gcol0) {
    __shared__ float red[4][64];
    int gi = blockIdx.x;
    int col = blockIdx.y * 64 + (threadIdx.x & 63);
    int rg = threadIdx.x >> 6;
    int i0 = g_gstart[gi], i1 = g_gstart[gi + 1];
    float m = -3.0e38f;
    for (int i = i0 + rg; i < i1; i += 4) m = fmaxf(m, x[(size_t)i * C + col]);
    red[rg][threadIdx.x & 63] = m;
    __syncthreads();
    if (rg == 0) {
        m = fmaxf(fmaxf(red[0][col & 63], red[1][col & 63]),
                  fmaxf(red[2][col & 63], red[3][col & 63]));
        g_g[gi * GCOLS + gcol0 + col] = m;
    }
}

// ---------------- head MLPs ----------------
__global__ void k_latent(const float* __restrict__ W, const float* __restrict__ b) {
    int gi = blockIdx.x;
    int warp = threadIdx.x >> 5, lane = threadIdx.x & 31;
    int j = blockIdx.y * 8 + warp;
    __shared__ float gs[GCOLS];
    for (int i = threadIdx.x; i < GCOLS; i += 256) gs[i] = g_g[gi * GCOLS + i];
    __syncthreads();
    float acc = 0.f;
    for (int k = lane; k < GCOLS; k += 32) acc += gs[k] * W[(size_t)j * GCOLS + k];
    #pragma unroll
    for (int o = 16; o; o >>= 1) acc += __shfl_xor_sync(0xffffffffu, acc, o);
    if (lane == 0) g_lat[gi * LATD + j] = acc + b[j];
}

__global__ void k_head(const float* __restrict__ muW, const float* __restrict__ mub,
                       const float* __restrict__ vW, const float* __restrict__ vb,
                       float* __restrict__ out) {
    int gi = blockIdx.x;
    int warp = threadIdx.x >> 5, lane = threadIdx.x & 31;
    int j = blockIdx.y * 8 + warp;
    __shared__ float ls[LATD];
    for (int i = threadIdx.x; i < LATD; i += 256) ls[i] = g_lat[gi * LATD + i];
    __syncthreads();
    float am = 0.f, av = 0.f;
    for (int k = lane; k < LATD; k += 32) {
        float l = ls[k];
        am += l * muW[(size_t)j * LATD + k];
        av += l * vW[(size_t)j * LATD + k];
    }
    #pragma unroll
    for (int o = 16; o; o >>= 1) {
        am += __shfl_xor_sync(0xffffffffu, am, o);
        av += __shfl_xor_sync(0xffffffffu, av, o);
    }
    if (lane == 0) {
        out[gi * LATD + j] = am + mub[j];
        out[NGR * LATD + gi * LATD + j] = av + vb[j];
    }
}

// ---------------- launch ----------------
extern "C" void kernel_launch(void* const* d_in, const int* in_sizes, int n_in,
                              void* d_out, int out_size) {
    const float* street  = (const float*)d_in[0];
    const float* build   = (const float*)d_in[1];
    const float* smask   = (const float*)d_in[2];
    const float* bmask   = (const float*)d_in[3];
    const int*   ei      = (const int*)d_in[4];
    const int*   batch   = (const int*)d_in[5];
    const float* sW      = (const float*)d_in[6];
    const float* sb      = (const float*)d_in[7];
    const float* bW      = (const float*)d_in[8];
    const float* bb      = (const float*)d_in[9];
    const float* W1      = (const float*)d_in[10];
    const float* as1     = (const float*)d_in[11];
    const float* ad1     = (const float*)d_in[12];
    const float* b1      = (const float*)d_in[13];
    const float* W2      = (const float*)d_in[14];
    const float* as2     = (const float*)d_in[15];
    const float* ad2     = (const float*)d_in[16];
    const float* b2      = (const float*)d_in[17];
    const float* W3      = (const float*)d_in[18];
    const float* as3     = (const float*)d_in[19];
    const float* ad3     = (const float*)d_in[20];
    const float* b3      = (const float*)d_in[21];
    const float* aggW    = (const float*)d_in[22];
    const float* aggb    = (const float*)d_in[23];
    const float* muW     = (const float*)d_in[24];
    const float* mub     = (const float*)d_in[25];
    const float* varW    = (const float*)d_in[26];
    const float* varb    = (const float*)d_in[27];
    float* out = (float*)d_out;

    int E = in_sizes[4] / 2;

    float *n0, *n1, *n2, *n3;
    cudaGetSymbolAddress((void**)&n0, g_n0);
    cudaGetSymbolAddress((void**)&n1, g_n1);
    cudaGetSymbolAddress((void**)&n2, g_n2);
    cudaGetSymbolAddress((void**)&n3, g_n3);

    dim3 ggrid((NN + 127) / 128, 2);

    // 0: encode (also zeroes g_deg)
    k_encode<<<(NN + ENB - 1) / ENB, 256>>>(street, build, smask, bmask, sW, sb, bW, bb);
    // 1: hist
    k_hist<<<(E + 255) / 256, 256>>>(ei, E);
    // 2: block sums
    k_scan1<<<NBLK, 256>>>();
    // 3: layer-1 GEMM (PROFILED LAUNCH)
    k_gemm<<<ggrid, 256>>>(n0, W1, FD, as1, ad1);
    // 4: scan finalize
    k_scan3<<<NBLK, 256>>>(E, NBLK);
    // 5: scatter (+ graph bounds)
    k_scatter<<<(E + 255) / 256, 256>>>(ei, batch, E);
    // 6: agg L1
    k_agg<<<(NN + 7) / 8, 256>>>(b1, n1);
    // 7-8: layer 2
    k_gemm<<<ggrid, 256>>>(n1, W2, HF, as2, ad2);
    k_agg<<<(NN + 7) / 8, 256>>>(b2, n2);
    // 9-10: layer 3
    k_gemm<<<ggrid, 256>>>(n2, W3, HF, as3, ad3);
    k_agg<<<(NN + 7) / 8, 256>>>(b3, n3);

    // pooling
    k_pool<<<dim3(NGR, 1), 256>>>(n0, FD, 0);
    k_pool<<<dim3(NGR, 4), 256>>>(n1, HF, FD);
    k_pool<<<dim3(NGR, 4), 256>>>(n2, HF, FD + HF);
    k_pool<<<dim3(NGR, 4), 256>>>(n3, HF, FD + 2 * HF);

    // head
    k_latent<<<dim3(NGR, LATD / 8), 256>>>(aggW, aggb);
    k_head<<<dim3(NGR, LATD / 8), 256>>>(muW, mub, varW, varb, out);
}

// round 5
// speedup vs baseline: 2.9193x; 1.1179x over previous
#include <cuda_runtime.h>
#include <math.h>
#include <stdint.h>

#define NN 20000
#define NE 320000
#define FD 64
#define NH 4
#define HF 256    // NH*FD
#define NGR 64
#define LATD 512
#define GCOLS 832  // FD*(1+3*NH)
#define NBLK ((NN + 255) / 256)   // 79 scan blocks (all co-resident)
#define ENB 64    // encode nodes per block
#define GEMMB 314 // gemm blocks: ceil(20000/128)*2
#define CAP 128   // cached edges per dst in k_agg

// ---------------- scratch (static device globals; no allocs) ----------------
__device__ float g_n0[NN * FD];
__device__ float g_n1[NN * HF];
__device__ float g_n2[NN * HF];
__device__ float g_n3[NN * HF];
__device__ float g_h [NN * HF];
__device__ float g_s [NN * NH];
__device__ float g_d [NN * NH];
__device__ int   g_deg[NN + 1];
__device__ int   g_off[NN + 1];
__device__ int   g_cur[NN];
__device__ int   g_csr[NE];
__device__ int   g_bsum[NBLK + 1];
__device__ int   g_ctr1;
__device__ int   g_ctr2;
__device__ int   g_gstart[NGR + 1];
__device__ float g_g[NGR * GCOLS];
__device__ float g_lat[NGR * LATD];

__device__ __forceinline__ float leaky(float x) { return x > 0.f ? x : 0.2f * x; }

__device__ __forceinline__ void cpa16(uint32_t dst, const void* src, bool p) {
    asm volatile("cp.async.ca.shared.global [%0], [%1], 16, %2;"
                 :: "r"(dst), "l"(src), "r"(p ? 16 : 0));
}

// ---------------- encode + edge histogram (fused) ----------------
__global__ void __launch_bounds__(256) k_enchist(
        const float* __restrict__ sf, const float* __restrict__ bfeat,
        const float* __restrict__ sm, const float* __restrict__ bm,
        const float* __restrict__ sW, const float* __restrict__ sb,
        const float* __restrict__ bW, const float* __restrict__ bb,
        const int* __restrict__ ei, int E) {
    __shared__ float sWs[64 * 132];
    __shared__ float bWs[64 * 5];
    __shared__ float sbs[64], bbs[64];
    __shared__ float xbs[ENB * 5];
    int t = threadIdx.x;
    int node0 = blockIdx.x * ENB;

    // histogram (grid-stride over edges); relies on g_deg zeroed (init/prev replay)
    for (int i = blockIdx.x * 256 + t; i < E; i += gridDim.x * 256)
        atomicAdd(&g_deg[ei[E + i]], 1);

    for (int l = t; l < 64 * 32; l += 256) {
        int r = l >> 5, c = l & 31;
        float4 v = *(const float4*)(sW + r * 128 + c * 4);
        *(float4*)&sWs[r * 132 + c * 4] = v;
    }
    if (t < 64) { sbs[t] = sb[t]; bbs[t] = bb[t]; }
    for (int l = t; l < 320; l += 256) bWs[l] = bW[l];
    for (int l = t; l < ENB * 5; l += 256) {
        int n = l / 5, c = l % 5;
        int g = node0 + n;
        xbs[l] = (g < NN) ? bfeat[g * 5 + c] : 0.f;
    }
    __syncthreads();

    int f = t & 63, slot = t >> 6;
    float acc[16];
    #pragma unroll
    for (int i = 0; i < 16; i++) acc[i] = 0.f;

    #pragma unroll
    for (int kc = 0; kc < 16; kc++) {
        float4 w0 = *(float4*)&sWs[f * 132 + kc * 8];
        float4 w1 = *(float4*)&sWs[f * 132 + kc * 8 + 4];
        #pragma unroll
        for (int ni = 0; ni < 16; ni++) {
            int g = node0 + slot * 16 + ni;
            int gc = (g < NN) ? g : (NN - 1);
            const float4* xp = (const float4*)(sf + (size_t)gc * 128 + kc * 8);
            float4 x0 = xp[0], x1 = xp[1];
            acc[ni] += w0.x * x0.x + w0.y * x0.y + w0.z * x0.z + w0.w * x0.w
                     + w1.x * x1.x + w1.y * x1.y + w1.z * x1.z + w1.w * x1.w;
        }
    }
    #pragma unroll
    for (int ni = 0; ni < 16; ni++) {
        int n = slot * 16 + ni;
        int g = node0 + n;
        if (g < NN) {
            float accS = fmaxf(acc[ni] + sbs[f], 0.f);
            float accB = bbs[f];
            #pragma unroll
            for (int i = 0; i < 5; i++) accB += xbs[n * 5 + i] * bWs[f * 5 + i];
            accB = fmaxf(accB, 0.f);
            g_n0[(size_t)g * FD + f] = accS * sm[g] + accB * bm[g];
        }
    }
}

// ---------------- single-kernel scan (79 blocks co-resident, spin barrier) ----------------
__global__ void __launch_bounds__(256) k_scan(int E) {
    __shared__ int wsum[8];
    __shared__ int pre_s;
    int b = blockIdx.x, tid = threadIdx.x, lane = tid & 31, w = tid >> 5;
    int i = b * 256 + tid;
    int v = (i < NN) ? g_deg[i] : 0;
    int x = v;
    #pragma unroll
    for (int o = 1; o < 32; o <<= 1) {
        int y = __shfl_up_sync(0xffffffffu, x, o);
        if (lane >= o) x += y;
    }
    if (lane == 31) wsum[w] = x;
    __syncthreads();
    if (tid < 8) {
        int t2 = wsum[tid];
        #pragma unroll
        for (int o = 1; o < 8; o <<= 1) {
            int y = __shfl_up_sync(0xffu, t2, o);
            if (tid >= o) t2 += y;
        }
        wsum[tid] = t2;
    }
    __syncthreads();
    int excl = x - v + (w > 0 ? wsum[w - 1] : 0);

    if (tid == 255) {
        g_bsum[b] = excl + v;
        __threadfence();
        atomicAdd(&g_ctr1, 1);
    }
    if (tid == 0) {
        while (atomicAdd(&g_ctr1, 0) < NBLK) __nanosleep(64);
    }
    __syncthreads();
    __threadfence();

    if (tid < 32) {
        int s = 0;
        for (int j = tid; j < b; j += 32) s += g_bsum[j];
        #pragma unroll
        for (int o = 16; o; o >>= 1) s += __shfl_xor_sync(0xffffffffu, s, o);
        if (tid == 0) pre_s = s;
    }
    __syncthreads();
    if (i < NN) {
        int o = excl + pre_s;
        g_off[i] = o;
        g_cur[i] = o;
    }
    if (i == 0) g_off[NN] = E;
    __syncthreads();
    if (tid == 0) {
        int old = atomicAdd(&g_ctr2, 1);
        if (old == NBLK - 1) { g_ctr1 = 0; __threadfence(); g_ctr2 = 0; __threadfence(); }
    }
}

// ---------------- tf32 mma GEMM body (cp.async 2-stage) + fused s/d logits ----------------
// g_h[M,256] = A[M,K] @ W[256,K]^T, raw f32 bits fed to tf32 mma (HW truncates)
__device__ __forceinline__ void gemm_body(float* smemf,
        const float* __restrict__ A, const float* __restrict__ W, int Kdim,
        const float* __restrict__ as_, const float* __restrict__ ad_, int bx) {
    int tid = threadIdx.x;
    int lane = tid & 31, warp = tid >> 5;
    int warpM = warp >> 1, warpN = warp & 1;
    int mi = bx >> 1, ni = bx & 1;
    int bm = mi * 128, bn = ni * 128;
    int gid = lane >> 2, tig = lane & 3;
    uint32_t smb = (uint32_t)__cvta_generic_to_shared(smemf);

    float acc[2][8][4];
    #pragma unroll
    for (int mt = 0; mt < 2; mt++)
        #pragma unroll
        for (int nt = 0; nt < 8; nt++)
            #pragma unroll
            for (int j = 0; j < 4; j++) acc[mt][nt][j] = 0.f;

    int nk = Kdim >> 5;

    // stage layout: As(s): smemf + s*4608 ([128][36]); Bs(s): smemf + 9216 + s*4608
    #define COPY_STAGE(ii, ss) do {                                              \
        int k0_ = (ii) * 32;                                                     \
        _Pragma("unroll")                                                        \
        for (int l = 0; l < 4; l++) {                                            \
            int idx = tid + 256 * l;                                             \
            int row = idx >> 3, k4 = idx & 7;                                    \
            int gr = bm + row;                                                   \
            bool p = gr < NN;                                                    \
            int grc = p ? gr : (NN - 1);                                         \
            cpa16(smb + ((ss) * 4608 + row * 36 + k4 * 4) * 4,                   \
                  A + (size_t)grc * Kdim + k0_ + k4 * 4, p);                     \
            cpa16(smb + (9216 + (ss) * 4608 + row * 36 + k4 * 4) * 4,            \
                  W + (size_t)(bn + row) * Kdim + k0_ + k4 * 4, true);           \
        }                                                                        \
        asm volatile("cp.async.commit_group;");                                  \
    } while (0)

    COPY_STAGE(0, 0);

    for (int i = 0; i < nk; i++) {
        asm volatile("cp.async.wait_group 0;");
        __syncthreads();
        if (i + 1 < nk) COPY_STAGE(i + 1, (i + 1) & 1);

        const float* As_ = smemf + (i & 1) * 4608;
        const float* Bs_ = smemf + 9216 + (i & 1) * 4608;
        #pragma unroll
        for (int k8 = 0; k8 < 4; k8++) {
            unsigned a[2][4];
            int col = k8 * 8 + tig;
            #pragma unroll
            for (int mt = 0; mt < 2; mt++) {
                int row = warpM * 32 + mt * 16 + gid;
                a[mt][0] = __float_as_uint(As_[row * 36 + col]);
                a[mt][1] = __float_as_uint(As_[(row + 8) * 36 + col]);
                a[mt][2] = __float_as_uint(As_[row * 36 + col + 4]);
                a[mt][3] = __float_as_uint(As_[(row + 8) * 36 + col + 4]);
            }
            #pragma unroll
            for (int nt = 0; nt < 8; nt++) {
                int colB = warpN * 64 + nt * 8 + gid;
                int rowB = k8 * 8 + tig;
                unsigned b0 = __float_as_uint(Bs_[colB * 36 + rowB]);
                unsigned b1 = __float_as_uint(Bs_[colB * 36 + rowB + 4]);
                #pragma unroll
                for (int mt = 0; mt < 2; mt++) {
                    asm volatile(
                        "mma.sync.aligned.m16n8k8.row.col.f32.tf32.tf32.f32 "
                        "{%0,%1,%2,%3}, {%4,%5,%6,%7}, {%8,%9}, {%0,%1,%2,%3};"
                        : "+f"(acc[mt][nt][0]), "+f"(acc[mt][nt][1]),
                          "+f"(acc[mt][nt][2]), "+f"(acc[mt][nt][3])
                        : "r"(a[mt][0]), "r"(a[mt][1]), "r"(a[mt][2]), "r"(a[mt][3]),
                          "r"(b0), "r"(b1));
                }
            }
        }
        __syncthreads();
    }
    #undef COPY_STAGE

    // epilogue: write h + fused s/d attention logits
    int hd = (bn >> 6) + warpN;
    #pragma unroll
    for (int mt = 0; mt < 2; mt++) {
        int row0 = bm + warpM * 32 + mt * 16 + gid;
        float sp0 = 0.f, sp8 = 0.f, dp0 = 0.f, dp8 = 0.f;
        #pragma unroll
        for (int nt = 0; nt < 8; nt++) {
            int col = bn + warpN * 64 + nt * 8 + tig * 2;
            int lc = nt * 8 + tig * 2;
            float2 a2s = *(const float2*)(as_ + hd * 64 + lc);
            float2 a2d = *(const float2*)(ad_ + hd * 64 + lc);
            sp0 += acc[mt][nt][0] * a2s.x + acc[mt][nt][1] * a2s.y;
            sp8 += acc[mt][nt][2] * a2s.x + acc[mt][nt][3] * a2s.y;
            dp0 += acc[mt][nt][0] * a2d.x + acc[mt][nt][1] * a2d.y;
            dp8 += acc[mt][nt][2] * a2d.x + acc[mt][nt][3] * a2d.y;
            if (row0 < NN)
                *(float2*)(g_h + (size_t)row0 * HF + col) =
                    make_float2(acc[mt][nt][0], acc[mt][nt][1]);
            if (row0 + 8 < NN)
                *(float2*)(g_h + (size_t)(row0 + 8) * HF + col) =
                    make_float2(acc[mt][nt][2], acc[mt][nt][3]);
        }
        #pragma unroll
        for (int o = 1; o < 4; o <<= 1) {
            sp0 += __shfl_xor_sync(0xffffffffu, sp0, o);
            sp8 += __shfl_xor_sync(0xffffffffu, sp8, o);
            dp0 += __shfl_xor_sync(0xffffffffu, dp0, o);
            dp8 += __shfl_xor_sync(0xffffffffu, dp8, o);
        }
        if (tig == 0) {
            if (row0 < NN)     { g_s[row0 * NH + hd] = sp0; g_d[row0 * NH + hd] = dp0; }
            if (row0 + 8 < NN) { g_s[(row0 + 8) * NH + hd] = sp8; g_d[(row0 + 8) * NH + hd] = dp8; }
        }
    }
}

__global__ void __launch_bounds__(256, 2) k_gemm(const float* __restrict__ A,
        const float* __restrict__ W, int Kdim,
        const float* __restrict__ as_, const float* __restrict__ ad_) {
    extern __shared__ float smemf[];
    gemm_body(smemf, A, W, Kdim, as_, ad_, blockIdx.x);
}

// gemm (blocks < GEMMB) + scatter/gbounds/deg-reset (remaining blocks), fused
__global__ void __launch_bounds__(256, 2) k_gemsc(const float* __restrict__ A,
        const float* __restrict__ W, int Kdim,
        const float* __restrict__ as_, const float* __restrict__ ad_,
        const int* __restrict__ ei, const int* __restrict__ batch, int E) {
    extern __shared__ float smemf[];
    if (blockIdx.x < GEMMB) {
        gemm_body(smemf, A, W, Kdim, as_, ad_, blockIdx.x);
        return;
    }
    int i = (blockIdx.x - GEMMB) * 256 + threadIdx.x;
    if (i <= NN) g_deg[i] = 0;   // reset for next replay
    if (i < E) {
        int dd = ei[E + i];
        int p = atomicAdd(&g_cur[dd], 1);
        g_csr[p] = ei[i];
    }
    if (i == 0) { g_gstart[0] = 0; g_gstart[NGR] = NN; }
    if (i > 0 && i < NN && batch[i] != batch[i - 1]) g_gstart[batch[i]] = i;
}

// ---------------- GAT aggregation: warp per dst, smem-cached logits + pipelined gathers
__global__ void __launch_bounds__(256) k_agg(const float* __restrict__ bias,
                                             float* __restrict__ xout) {
    __shared__ float4 sle[8][CAP + 4];
    __shared__ int    ssrc[8][CAP + 4];
    int warp = threadIdx.x >> 5, lane = threadIdx.x & 31;
    int dst = blockIdx.x * 8 + warp;
    if (dst >= NN) return;
    int e0 = g_off[dst], e1 = g_off[dst + 1];
    int n = e1 - e0;
    bool cached = (n <= CAP);
    float4 d4 = *(const float4*)(g_d + dst * NH);
    float4 s4self = *(const float4*)(g_s + dst * NH);

    // pass 1: per-head max + cache (src, leaky logits)
    float4 m;
    m.x = leaky(s4self.x + d4.x); m.y = leaky(s4self.y + d4.y);
    m.z = leaky(s4self.z + d4.z); m.w = leaky(s4self.w + d4.w);
    for (int j = lane; j < n; j += 32) {
        int src = g_csr[e0 + j];
        float4 s4 = *(const float4*)(g_s + src * NH);
        float4 le = make_float4(leaky(s4.x + d4.x), leaky(s4.y + d4.y),
                                leaky(s4.z + d4.z), leaky(s4.w + d4.w));
        m.x = fmaxf(m.x, le.x); m.y = fmaxf(m.y, le.y);
        m.z = fmaxf(m.z, le.z); m.w = fmaxf(m.w, le.w);
        if (cached) { ssrc[warp][j] = src; sle[warp][j] = le; }
    }
    #pragma unroll
    for (int o = 16; o; o >>= 1) {
        m.x = fmaxf(m.x, __shfl_xor_sync(0xffffffffu, m.x, o));
        m.y = fmaxf(m.y, __shfl_xor_sync(0xffffffffu, m.y, o));
        m.z = fmaxf(m.z, __shfl_xor_sync(0xffffffffu, m.z, o));
        m.w = fmaxf(m.w, __shfl_xor_sync(0xffffffffu, m.w, o));
    }

    int hd = lane >> 3;
    float mh  = (hd == 0) ? m.x : (hd == 1) ? m.y : (hd == 2) ? m.z : m.w;
    float ddh = (hd == 0) ? d4.x : (hd == 1) ? d4.y : (hd == 2) ? d4.z : d4.w;
    float ssl = (hd == 0) ? s4self.x : (hd == 1) ? s4self.y : (hd == 2) ? s4self.z : s4self.w;

    // self contribution
    float den, ac[8];
    {
        float w = __expf(leaky(ssl + ddh) - mh);
        den = w;
        const float4* hr = (const float4*)(g_h + (size_t)dst * HF) + lane * 2;
        float4 v0 = hr[0], v1 = hr[1];
        ac[0] = w * v0.x; ac[1] = w * v0.y; ac[2] = w * v0.z; ac[3] = w * v0.w;
        ac[4] = w * v1.x; ac[5] = w * v1.y; ac[6] = w * v1.z; ac[7] = w * v1.w;
    }

    if (cached) {
        if (lane < 4) {
            ssrc[warp][n + lane] = dst;   // pads: valid address, never accumulated
            sle[warp][n + lane] = make_float4(0.f, 0.f, 0.f, 0.f);
        }
        __syncwarp();
        int sA = ssrc[warp][0], sB = ssrc[warp][1];
        float4 leA = sle[warp][0], leB = sle[warp][1];
        const float4* hA = (const float4*)(g_h + (size_t)sA * HF) + lane * 2;
        const float4* hB = (const float4*)(g_h + (size_t)sB * HF) + lane * 2;
        float4 a0 = hA[0], a1 = hA[1], b0 = hB[0], b1 = hB[1];
        for (int j = 0; j < n; j += 2) {
            int sC = ssrc[warp][j + 2], sD = ssrc[warp][j + 3];
            float4 leC = sle[warp][j + 2], leD = sle[warp][j + 3];
            const float4* hC = (const float4*)(g_h + (size_t)sC * HF) + lane * 2;
            const float4* hD = (const float4*)(g_h + (size_t)sD * HF) + lane * 2;
            float4 c0 = hC[0], c1 = hC[1], d0 = hD[0], d1 = hD[1];
            float leAh = (hd == 0) ? leA.x : (hd == 1) ? leA.y : (hd == 2) ? leA.z : leA.w;
            float wA = __expf(leAh - mh);
            den += wA;
            ac[0] += wA * a0.x; ac[1] += wA * a0.y; ac[2] += wA * a0.z; ac[3] += wA * a0.w;
            ac[4] += wA * a1.x; ac[5] += wA * a1.y; ac[6] += wA * a1.z; ac[7] += wA * a1.w;
            if (j + 1 < n) {
                float leBh = (hd == 0) ? leB.x : (hd == 1) ? leB.y : (hd == 2) ? leB.z : leB.w;
                float wB = __expf(leBh - mh);
                den += wB;
                ac[0] += wB * b0.x; ac[1] += wB * b0.y; ac[2] += wB * b0.z; ac[3] += wB * b0.w;
                ac[4] += wB * b1.x; ac[5] += wB * b1.y; ac[6] += wB * b1.z; ac[7] += wB * b1.w;
            }
            leA = leC; leB = leD;
            a0 = c0; a1 = c1; b0 = d0; b1 = d1;
        }
    } else {
        // fallback: serial (deg > CAP; effectively never for this data)
        for (int e = e0; e < e1; e++) {
            int src = g_csr[e];
            float4 s4 = *(const float4*)(g_s + src * NH);
            float sh = (hd == 0) ? s4.x : (hd == 1) ? s4.y : (hd == 2) ? s4.z : s4.w;
            float w = __expf(leaky(sh + ddh) - mh);
            den += w;
            const float4* hr = (const float4*)(g_h + (size_t)src * HF) + lane * 2;
            float4 v0 = hr[0], v1 = hr[1];
            ac[0] += w * v0.x; ac[1] += w * v0.y; ac[2] += w * v0.z; ac[3] += w * v0.w;
            ac[4] += w * v1.x; ac[5] += w * v1.y; ac[6] += w * v1.z; ac[7] += w * v1.w;
        }
    }

    float inv = 1.f / den;
    int c = lane * 8;
    const float4* bp = (const float4*)(bias + c);
    float4 bb0 = bp[0], bb1 = bp[1];
    float4 o0 = make_float4(fmaxf(ac[0] * inv + bb0.x, 0.f), fmaxf(ac[1] * inv + bb0.y, 0.f),
                            fmaxf(ac[2] * inv + bb0.z, 0.f), fmaxf(ac[3] * inv + bb0.w, 0.f));
    float4 o1 = make_float4(fmaxf(ac[4] * inv + bb1.x, 0.f), fmaxf(ac[5] * inv + bb1.y, 0.f),
                            fmaxf(ac[6] * inv + bb1.z, 0.f), fmaxf(ac[7] * inv + bb1.w, 0.f));
    float4* op = (float4*)(xout + (size_t)dst * HF + c);
    op[0] = o0; op[1] = o1;
}

// ---------------- per-graph max pool ----------------
__global__ void k_pool(const float* __restrict__ x, int C, int gcol0) {
    __shared__ float red[4][64];
    int gi = blockIdx.x;
    int col = blockIdx.y * 64 + (threadIdx.x & 63);
    int rg = threadIdx.x >> 6;
    int i0 = g_gstart[gi], i1 = g_gstart[gi + 1];
    float m = -3.0e38f;
    for (int i = i0 + rg; i < i1; i += 4) m = fmaxf(m, x[(size_t)i * C + col]);
    red[rg][threadIdx.x & 63] = m;
    __syncthreads();
    if (rg == 0) {
        m = fmaxf(fmaxf(red[0][col & 63], red[1][col & 63]),
                  fmaxf(red[2][col & 63], red[3][col & 63]));
        g_g[gi * GCOLS + gcol0 + col] = m;
    }
}

// ---------------- head MLPs ----------------
__global__ void k_latent(const float* __restrict__ W, const float* __restrict__ b) {
    int gi = blockIdx.x;
    int warp = threadIdx.x >> 5, lane = threadIdx.x & 31;
    int j = blockIdx.y * 8 + warp;
    __shared__ float gs[GCOLS];
    for (int i = threadIdx.x; i < GCOLS; i += 256) gs[i] = g_g[gi * GCOLS + i];
    __syncthreads();
    float acc = 0.f;
    for (int k = lane; k < GCOLS; k += 32) acc += gs[k] * W[(size_t)j * GCOLS + k];
    #pragma unroll
    for (int o = 16; o; o >>= 1) acc += __shfl_xor_sync(0xffffffffu, acc, o);
    if (lane == 0) g_lat[gi * LATD + j] = acc + b[j];
}

__global__ void k_head(const float* __restrict__ muW, const float* __restrict__ mub,
                       const float* __restrict__ vW, const float* __restrict__ vb,
                       float* __restrict__ out) {
    int gi = blockIdx.x;
    int warp = threadIdx.x >> 5, lane = threadIdx.x & 31;
    int j = blockIdx.y * 8 + warp;
    __shared__ float ls[LATD];
    for (int i = threadIdx.x; i < LATD; i += 256) ls[i] = g_lat[gi * LATD + i];
    __syncthreads();
    float am = 0.f, av = 0.f;
    for (int k = lane; k < LATD; k += 32) {
        float l = ls[k];
        am += l * muW[(size_t)j * LATD + k];
        av += l * vW[(size_t)j * LATD + k];
    }
    #pragma unroll
    for (int o = 16; o; o >>= 1) {
        am += __shfl_xor_sync(0xffffffffu, am, o);
        av += __shfl_xor_sync(0xffffffffu, av, o);
    }
    if (lane == 0) {
        out[gi * LATD + j] = am + mub[j];
        out[NGR * LATD + gi * LATD + j] = av + vb[j];
    }
}

// ---------------- launch ----------------
extern "C" void kernel_launch(void* const* d_in, const int* in_sizes, int n_in,
                              void* d_out, int out_size) {
    const float* street  = (const float*)d_in[0];
    const float* build   = (const float*)d_in[1];
    const float* smask   = (const float*)d_in[2];
    const float* bmask   = (const float*)d_in[3];
    const int*   ei      = (const int*)d_in[4];
    const int*   batch   = (const int*)d_in[5];
    const float* sW      = (const float*)d_in[6];
    const float* sb      = (const float*)d_in[7];
    const float* bW      = (const float*)d_in[8];
    const float* bb      = (const float*)d_in[9];
    const float* W1      = (const float*)d_in[10];
    const float* as1     = (const float*)d_in[11];
    const float* ad1     = (const float*)d_in[12];
    const float* b1      = (const float*)d_in[13];
    const float* W2      = (const float*)d_in[14];
    const float* as2     = (const float*)d_in[15];
    const float* ad2     = (const float*)d_in[16];
    const float* b2      = (const float*)d_in[17];
    const float* W3      = (const float*)d_in[18];
    const float* as3     = (const float*)d_in[19];
    const float* ad3     = (const float*)d_in[20];
    const float* b3      = (const float*)d_in[21];
    const float* aggW    = (const float*)d_in[22];
    const float* aggb    = (const float*)d_in[23];
    const float* muW     = (const float*)d_in[24];
    const float* mub     = (const float*)d_in[25];
    const float* varW    = (const float*)d_in[26];
    const float* varb    = (const float*)d_in[27];
    float* out = (float*)d_out;

    int E = in_sizes[4] / 2;
    const int GSMEM = 4 * 128 * 36 * 4;  // 73728 B dynamic smem

    static int attr_set = 0;
    if (!attr_set) {
        cudaFuncSetAttribute(k_gemm, cudaFuncAttributeMaxDynamicSharedMemorySize, GSMEM);
        cudaFuncSetAttribute(k_gemsc, cudaFuncAttributeMaxDynamicSharedMemorySize, GSMEM);
        attr_set = 1;
    }

    float *n0, *n1, *n2, *n3;
    cudaGetSymbolAddress((void**)&n0, g_n0);
    cudaGetSymbolAddress((void**)&n1, g_n1);
    cudaGetSymbolAddress((void**)&n2, g_n2);
    cudaGetSymbolAddress((void**)&n3, g_n3);

    int scatB = (E + 255) / 256;

    // 0: encode + histogram
    k_enchist<<<(NN + ENB - 1) / ENB, 256>>>(street, build, smask, bmask,
                                             sW, sb, bW, bb, ei, E);
    // 1: fused scan (spin barrier, 79 co-resident blocks)
    k_scan<<<NBLK, 256>>>(E);
    // 2: layer-1 GEMM + scatter + gbounds + deg reset (fused)
    k_gemsc<<<GEMMB + scatB, 256, GSMEM>>>(n0, W1, FD, as1, ad1, ei, batch, E);
    // 3: agg L1 (PROFILED LAUNCH)
    k_agg<<<(NN + 7) / 8, 256>>>(b1, n1);
    // 4-5: layer 2
    k_gemm<<<GEMMB, 256, GSMEM>>>(n1, W2, HF, as2, ad2);
    k_agg<<<(NN + 7) / 8, 256>>>(b2, n2);
    // 6-7: layer 3
    k_gemm<<<GEMMB, 256, GSMEM>>>(n2, W3, HF, as3, ad3);
    k_agg<<<(NN + 7) / 8, 256>>>(b3, n3);

    // pooling
    k_pool<<<dim3(NGR, 1), 256>>>(n0, FD, 0);
    k_pool<<<dim3(NGR, 4), 256>>>(n1, HF, FD);
    k_pool<<<dim3(NGR, 4), 256>>>(n2, HF, FD + HF);
    k_pool<<<dim3(NGR, 4), 256>>>(n3, HF, FD + 2 * HF);

    // head
    k_latent<<<dim3(NGR, LATD / 8), 256>>>(aggW, aggb);
    k_head<<<dim3(NGR, LATD / 8), 256>>>(muW, mub, varW, varb, out);
}

// round 6
// speedup vs baseline: 3.6921x; 1.2647x over previous
#include <cuda_runtime.h>
#include <math.h>
#include <stdint.h>

#define NN 20000
#define NE 320000
#define FD 64
#define NH 4
#define HF 256    // NH*FD
#define NGR 64
#define LATD 512
#define GCOLS 832  // FD*(1+3*NH)
#define NBLK ((NN + 255) / 256)   // 79 scan blocks (all co-resident)
#define GEMMB 314 // gemm blocks: ceil(20000/128)*2
#define ENCB 157  // encode blocks: ceil(20000/128)
#define CAP 64    // cached edges per dst in k_agg

// ---------------- scratch (static device globals; no allocs) ----------------
__device__ float g_n0[NN * FD];
__device__ float g_n1[NN * HF];
__device__ float g_n2[NN * HF];
__device__ float g_n3[NN * HF];
__device__ float g_h [NN * HF];
__device__ float g_s [NN * NH];
__device__ float g_d [NN * NH];
__device__ int   g_deg[NN + 1];
__device__ int   g_off[NN + 1];
__device__ int   g_cur[NN];
__device__ int   g_csr[NE];
__device__ int   g_bsum[NBLK + 1];
__device__ int   g_ctrA;
__device__ int   g_ctrB;
__device__ int   g_gstart[NGR + 1];
__device__ float g_g[NGR * GCOLS];
__device__ float g_lat[NGR * LATD];

__device__ __forceinline__ float leaky(float x) { return x > 0.f ? x : 0.2f * x; }

__device__ __forceinline__ void cpa16(uint32_t dst, const void* src, bool p) {
    asm volatile("cp.async.ca.shared.global [%0], [%1], 16, %2;"
                 :: "r"(dst), "l"(src), "r"(p ? 16 : 0));
}

// ---------------- encode via tf32 mma: n0 = relu(sf@sW^T+sb)*sm + relu(bf@bW^T+bb)*bm
// also: edge histogram + barrier-counter reset
__global__ void __launch_bounds__(256) k_encode2(
        const float* __restrict__ sf, const float* __restrict__ bfeat,
        const float* __restrict__ smk, const float* __restrict__ bmk,
        const float* __restrict__ sW, const float* __restrict__ sb,
        const float* __restrict__ bW, const float* __restrict__ bb,
        const int* __restrict__ ei, int E) {
    extern __shared__ float smem[];
    // layout (floats): As 2x4608 @0, Bs 2x2304 @9216, sbs @13824, bbs @13888, bWs @13952
    float* sbs = smem + 13824;
    float* bbs = smem + 13888;
    float* bWs = smem + 13952;
    int tid = threadIdx.x;
    int lane = tid & 31, warp = tid >> 5;
    int warpM = warp >> 1, warpN = warp & 1;
    int bm = blockIdx.x * 128;
    int gid = lane >> 2, tig = lane & 3;
    uint32_t smb = (uint32_t)__cvta_generic_to_shared(smem);

    if (blockIdx.x == 0 && tid == 0) { g_ctrA = 0; g_ctrB = 0; }

    // edge histogram (grid-stride); g_deg zeroed by prior replay's k_scan (or init)
    for (int i = blockIdx.x * 256 + tid; i < E; i += ENCB * 256)
        atomicAdd(&g_deg[ei[E + i]], 1);

    if (tid < 64) { sbs[tid] = sb[tid]; bbs[tid] = bb[tid]; }
    for (int l = tid; l < 320; l += 256) bWs[l] = bW[l];

    float acc[2][4][4];
    #pragma unroll
    for (int mt = 0; mt < 2; mt++)
        #pragma unroll
        for (int nt = 0; nt < 4; nt++)
            #pragma unroll
            for (int j = 0; j < 4; j++) acc[mt][nt][j] = 0.f;

    #define ECOPY(ii, ss) do {                                                   \
        int k0_ = (ii) * 32;                                                     \
        _Pragma("unroll")                                                        \
        for (int l = 0; l < 4; l++) {                                            \
            int idx = tid + 256 * l;                                             \
            int row = idx >> 3, k4 = idx & 7;                                    \
            int gr = bm + row;                                                   \
            bool p = gr < NN;                                                    \
            int grc = p ? gr : (NN - 1);                                         \
            cpa16(smb + ((ss) * 4608 + row * 36 + k4 * 4) * 4,                   \
                  sf + (size_t)grc * 128 + k0_ + k4 * 4, p);                     \
        }                                                                        \
        _Pragma("unroll")                                                        \
        for (int l = 0; l < 2; l++) {                                            \
            int idx = tid + 256 * l;                                             \
            int row = idx >> 3, k4 = idx & 7;                                    \
            cpa16(smb + (9216 + (ss) * 2304 + row * 36 + k4 * 4) * 4,            \
                  sW + (size_t)row * 128 + k0_ + k4 * 4, true);                  \
        }                                                                        \
        asm volatile("cp.async.commit_group;");                                  \
    } while (0)

    ECOPY(0, 0);
    for (int i = 0; i < 4; i++) {
        asm volatile("cp.async.wait_group 0;");
        __syncthreads();
        if (i + 1 < 4) ECOPY(i + 1, (i + 1) & 1);
        const float* As_ = smem + (i & 1) * 4608;
        const float* Bs_ = smem + 9216 + (i & 1) * 2304;
        #pragma unroll
        for (int k8 = 0; k8 < 4; k8++) {
            unsigned a[2][4];
            int col = k8 * 8 + tig;
            #pragma unroll
            for (int mt = 0; mt < 2; mt++) {
                int row = warpM * 32 + mt * 16 + gid;
                a[mt][0] = __float_as_uint(As_[row * 36 + col]);
                a[mt][1] = __float_as_uint(As_[(row + 8) * 36 + col]);
                a[mt][2] = __float_as_uint(As_[row * 36 + col + 4]);
                a[mt][3] = __float_as_uint(As_[(row + 8) * 36 + col + 4]);
            }
            #pragma unroll
            for (int nt = 0; nt < 4; nt++) {
                int colB = warpN * 32 + nt * 8 + gid;
                int rowB = k8 * 8 + tig;
                unsigned b0 = __float_as_uint(Bs_[colB * 36 + rowB]);
                unsigned b1 = __float_as_uint(Bs_[colB * 36 + rowB + 4]);
                #pragma unroll
                for (int mt = 0; mt < 2; mt++) {
                    asm volatile(
                        "mma.sync.aligned.m16n8k8.row.col.f32.tf32.tf32.f32 "
                        "{%0,%1,%2,%3}, {%4,%5,%6,%7}, {%8,%9}, {%0,%1,%2,%3};"
                        : "+f"(acc[mt][nt][0]), "+f"(acc[mt][nt][1]),
                          "+f"(acc[mt][nt][2]), "+f"(acc[mt][nt][3])
                        : "r"(a[mt][0]), "r"(a[mt][1]), "r"(a[mt][2]), "r"(a[mt][3]),
                          "r"(b0), "r"(b1));
                }
            }
        }
        __syncthreads();
    }
    #undef ECOPY

    // epilogue: relu/mask/building combine
    #pragma unroll
    for (int mt = 0; mt < 2; mt++) {
        int row0 = bm + warpM * 32 + mt * 16 + gid;
        int r1 = row0 + 8;
        int rc0 = (row0 < NN) ? row0 : (NN - 1);
        int rc1 = (r1 < NN) ? r1 : (NN - 1);
        float bf0[5], bf1[5];
        #pragma unroll
        for (int i = 0; i < 5; i++) { bf0[i] = bfeat[rc0 * 5 + i]; bf1[i] = bfeat[rc1 * 5 + i]; }
        float sm0 = smk[rc0], bm0 = bmk[rc0], sm1 = smk[rc1], bm1 = bmk[rc1];
        #pragma unroll
        for (int nt = 0; nt < 4; nt++) {
            int col = warpN * 32 + nt * 8 + tig * 2;
            float o0[2], o1[2];
            #pragma unroll
            for (int c = 0; c < 2; c++) {
                int f = col + c;
                float aS0 = fmaxf(acc[mt][nt][c] + sbs[f], 0.f);
                float aS1 = fmaxf(acc[mt][nt][2 + c] + sbs[f], 0.f);
                float aB0 = bbs[f], aB1 = bbs[f];
                #pragma unroll
                for (int i = 0; i < 5; i++) {
                    aB0 += bf0[i] * bWs[f * 5 + i];
                    aB1 += bf1[i] * bWs[f * 5 + i];
                }
                aB0 = fmaxf(aB0, 0.f); aB1 = fmaxf(aB1, 0.f);
                o0[c] = aS0 * sm0 + aB0 * bm0;
                o1[c] = aS1 * sm1 + aB1 * bm1;
            }
            if (row0 < NN) *(float2*)(g_n0 + (size_t)row0 * FD + col) = make_float2(o0[0], o0[1]);
            if (r1 < NN)   *(float2*)(g_n0 + (size_t)r1 * FD + col)   = make_float2(o1[0], o1[1]);
        }
    }
}

// ---------------- grid barrier for k_scan (79 co-resident blocks) ----------------
__device__ __forceinline__ void gbarrier(int* ctr) {
    __threadfence();
    __syncthreads();
    if (threadIdx.x == 0) {
        atomicAdd(ctr, 1);
        while (atomicAdd(ctr, 0) < NBLK) __nanosleep(32);
        __threadfence();
    }
    __syncthreads();
}

// ---------------- scan + scatter + gbounds + deg reset (single kernel) ----------------
__global__ void __launch_bounds__(256) k_scan(const int* __restrict__ ei,
                                              const int* __restrict__ batch, int E) {
    __shared__ int wsum[8];
    __shared__ int pre_s;
    int b = blockIdx.x, tid = threadIdx.x, lane = tid & 31, w = tid >> 5;
    int i = b * 256 + tid;
    int v = (i < NN) ? g_deg[i] : 0;
    int x = v;
    #pragma unroll
    for (int o = 1; o < 32; o <<= 1) {
        int y = __shfl_up_sync(0xffffffffu, x, o);
        if (lane >= o) x += y;
    }
    if (lane == 31) wsum[w] = x;
    __syncthreads();
    if (tid < 8) {
        int t2 = wsum[tid];
        #pragma unroll
        for (int o = 1; o < 8; o <<= 1) {
            int y = __shfl_up_sync(0xffu, t2, o);
            if (tid >= o) t2 += y;
        }
        wsum[tid] = t2;
    }
    __syncthreads();
    int excl = x - v + (w > 0 ? wsum[w - 1] : 0);
    if (tid == 255) g_bsum[b] = excl + v;

    gbarrier(&g_ctrA);

    if (tid < 32) {
        int s = 0;
        for (int j = tid; j < b; j += 32) s += g_bsum[j];
        #pragma unroll
        for (int o = 16; o; o >>= 1) s += __shfl_xor_sync(0xffffffffu, s, o);
        if (tid == 0) pre_s = s;
    }
    __syncthreads();
    if (i < NN) {
        int o = excl + pre_s;
        g_off[i] = o;
        g_cur[i] = o;
        g_deg[i] = 0;   // reset for next replay (safe: g_deg reads done pre-barrier)
    }
    if (i == 0) { g_off[NN] = E; g_gstart[0] = 0; g_gstart[NGR] = NN; }

    gbarrier(&g_ctrB);

    // scatter (needs all g_cur initialized)
    for (int e = b * 256 + tid; e < E; e += NBLK * 256) {
        int dd = ei[E + e];
        int p = atomicAdd(&g_cur[dd], 1);
        g_csr[p] = ei[e];
    }
    // graph boundaries
    for (int j = b * 256 + tid; j < NN; j += NBLK * 256) {
        if (j > 0 && batch[j] != batch[j - 1]) g_gstart[batch[j]] = j;
    }
}

// ---------------- tf32 mma GEMM (cp.async 2-stage) + fused s/d logits ----------------
__global__ void __launch_bounds__(256, 2) k_gemm(const float* __restrict__ A,
        const float* __restrict__ W, int Kdim,
        const float* __restrict__ as_, const float* __restrict__ ad_) {
    extern __shared__ float smemf[];
    int tid = threadIdx.x;
    int lane = tid & 31, warp = tid >> 5;
    int warpM = warp >> 1, warpN = warp & 1;
    int mi = blockIdx.x >> 1, ni = blockIdx.x & 1;
    int bm = mi * 128, bn = ni * 128;
    int gid = lane >> 2, tig = lane & 3;
    uint32_t smb = (uint32_t)__cvta_generic_to_shared(smemf);

    float acc[2][8][4];
    #pragma unroll
    for (int mt = 0; mt < 2; mt++)
        #pragma unroll
        for (int nt = 0; nt < 8; nt++)
            #pragma unroll
            for (int j = 0; j < 4; j++) acc[mt][nt][j] = 0.f;

    int nk = Kdim >> 5;

    #define COPY_STAGE(ii, ss) do {                                              \
        int k0_ = (ii) * 32;                                                     \
        _Pragma("unroll")                                                        \
        for (int l = 0; l < 4; l++) {                                            \
            int idx = tid + 256 * l;                                             \
            int row = idx >> 3, k4 = idx & 7;                                    \
            int gr = bm + row;                                                   \
            bool p = gr < NN;                                                    \
            int grc = p ? gr : (NN - 1);                                         \
            cpa16(smb + ((ss) * 4608 + row * 36 + k4 * 4) * 4,                   \
                  A + (size_t)grc * Kdim + k0_ + k4 * 4, p);                     \
            cpa16(smb + (9216 + (ss) * 4608 + row * 36 + k4 * 4) * 4,            \
                  W + (size_t)(bn + row) * Kdim + k0_ + k4 * 4, true);           \
        }                                                                        \
        asm volatile("cp.async.commit_group;");                                  \
    } while (0)

    COPY_STAGE(0, 0);

    for (int i = 0; i < nk; i++) {
        asm volatile("cp.async.wait_group 0;");
        __syncthreads();
        if (i + 1 < nk) COPY_STAGE(i + 1, (i + 1) & 1);

        const float* As_ = smemf + (i & 1) * 4608;
        const float* Bs_ = smemf + 9216 + (i & 1) * 4608;
        #pragma unroll
        for (int k8 = 0; k8 < 4; k8++) {
            unsigned a[2][4];
            int col = k8 * 8 + tig;
            #pragma unroll
            for (int mt = 0; mt < 2; mt++) {
                int row = warpM * 32 + mt * 16 + gid;
                a[mt][0] = __float_as_uint(As_[row * 36 + col]);
                a[mt][1] = __float_as_uint(As_[(row + 8) * 36 + col]);
                a[mt][2] = __float_as_uint(As_[row * 36 + col + 4]);
                a[mt][3] = __float_as_uint(As_[(row + 8) * 36 + col + 4]);
            }
            #pragma unroll
            for (int nt = 0; nt < 8; nt++) {
                int colB = warpN * 64 + nt * 8 + gid;
                int rowB = k8 * 8 + tig;
                unsigned b0 = __float_as_uint(Bs_[colB * 36 + rowB]);
                unsigned b1 = __float_as_uint(Bs_[colB * 36 + rowB + 4]);
                #pragma unroll
                for (int mt = 0; mt < 2; mt++) {
                    asm volatile(
                        "mma.sync.aligned.m16n8k8.row.col.f32.tf32.tf32.f32 "
                        "{%0,%1,%2,%3}, {%4,%5,%6,%7}, {%8,%9}, {%0,%1,%2,%3};"
                        : "+f"(acc[mt][nt][0]), "+f"(acc[mt][nt][1]),
                          "+f"(acc[mt][nt][2]), "+f"(acc[mt][nt][3])
                        : "r"(a[mt][0]), "r"(a[mt][1]), "r"(a[mt][2]), "r"(a[mt][3]),
                          "r"(b0), "r"(b1));
                }
            }
        }
    }
    #undef COPY_STAGE
    __syncthreads();

    // epilogue: write h + fused s/d attention logits
    int hd = (bn >> 6) + warpN;
    #pragma unroll
    for (int mt = 0; mt < 2; mt++) {
        int row0 = bm + warpM * 32 + mt * 16 + gid;
        float sp0 = 0.f, sp8 = 0.f, dp0 = 0.f, dp8 = 0.f;
        #pragma unroll
        for (int nt = 0; nt < 8; nt++) {
            int col = bn + warpN * 64 + nt * 8 + tig * 2;
            int lc = nt * 8 + tig * 2;
            float2 a2s = *(const float2*)(as_ + hd * 64 + lc);
            float2 a2d = *(const float2*)(ad_ + hd * 64 + lc);
            sp0 += acc[mt][nt][0] * a2s.x + acc[mt][nt][1] * a2s.y;
            sp8 += acc[mt][nt][2] * a2s.x + acc[mt][nt][3] * a2s.y;
            dp0 += acc[mt][nt][0] * a2d.x + acc[mt][nt][1] * a2d.y;
            dp8 += acc[mt][nt][2] * a2d.x + acc[mt][nt][3] * a2d.y;
            if (row0 < NN)
                *(float2*)(g_h + (size_t)row0 * HF + col) =
                    make_float2(acc[mt][nt][0], acc[mt][nt][1]);
            if (row0 + 8 < NN)
                *(float2*)(g_h + (size_t)(row0 + 8) * HF + col) =
                    make_float2(acc[mt][nt][2], acc[mt][nt][3]);
        }
        #pragma unroll
        for (int o = 1; o < 4; o <<= 1) {
            sp0 += __shfl_xor_sync(0xffffffffu, sp0, o);
            sp8 += __shfl_xor_sync(0xffffffffu, sp8, o);
            dp0 += __shfl_xor_sync(0xffffffffu, dp0, o);
            dp8 += __shfl_xor_sync(0xffffffffu, dp8, o);
        }
        if (tig == 0) {
            if (row0 < NN)     { g_s[row0 * NH + hd] = sp0; g_d[row0 * NH + hd] = dp0; }
            if (row0 + 8 < NN) { g_s[(row0 + 8) * NH + hd] = sp8; g_d[(row0 + 8) * NH + hd] = dp8; }
        }
    }
}

// ---------------- GAT aggregation: warp per dst, smem-cached logits, occupancy-driven
__global__ void __launch_bounds__(256, 4) k_agg(const float* __restrict__ bias,
                                                float* __restrict__ xout) {
    __shared__ float4 sle[8][CAP + 1];
    __shared__ int    ssrc[8][CAP + 1];
    int warp = threadIdx.x >> 5, lane = threadIdx.x & 31;
    int dst = blockIdx.x * 8 + warp;
    if (dst >= NN) return;
    int e0 = g_off[dst], e1 = g_off[dst + 1];
    int n = e1 - e0;
    bool cached = (n <= CAP);
    float4 d4 = *(const float4*)(g_d + dst * NH);
    float4 s4self = *(const float4*)(g_s + dst * NH);

    // pass 1: per-head max + cache (src, leaky logits)
    float4 m;
    m.x = leaky(s4self.x + d4.x); m.y = leaky(s4self.y + d4.y);
    m.z = leaky(s4self.z + d4.z); m.w = leaky(s4self.w + d4.w);
    for (int j = lane; j < n; j += 32) {
        int src = g_csr[e0 + j];
        float4 s4 = *(const float4*)(g_s + src * NH);
        float4 le = make_float4(leaky(s4.x + d4.x), leaky(s4.y + d4.y),
                                leaky(s4.z + d4.z), leaky(s4.w + d4.w));
        m.x = fmaxf(m.x, le.x); m.y = fmaxf(m.y, le.y);
        m.z = fmaxf(m.z, le.z); m.w = fmaxf(m.w, le.w);
        if (cached) { ssrc[warp][j] = src; sle[warp][j] = le; }
    }
    #pragma unroll
    for (int o = 16; o; o >>= 1) {
        m.x = fmaxf(m.x, __shfl_xor_sync(0xffffffffu, m.x, o));
        m.y = fmaxf(m.y, __shfl_xor_sync(0xffffffffu, m.y, o));
        m.z = fmaxf(m.z, __shfl_xor_sync(0xffffffffu, m.z, o));
        m.w = fmaxf(m.w, __shfl_xor_sync(0xffffffffu, m.w, o));
    }

    int hd = lane >> 3;
    float mh  = (hd == 0) ? m.x : (hd == 1) ? m.y : (hd == 2) ? m.z : m.w;
    float ddh = (hd == 0) ? d4.x : (hd == 1) ? d4.y : (hd == 2) ? d4.z : d4.w;
    float ssl = (hd == 0) ? s4self.x : (hd == 1) ? s4self.y : (hd == 2) ? s4self.z : s4self.w;

    // self contribution
    float den, ac[8];
    {
        float w = __expf(leaky(ssl + ddh) - mh);
        den = w;
        const float4* hr = (const float4*)(g_h + (size_t)dst * HF) + lane * 2;
        float4 v0 = hr[0], v1 = hr[1];
        ac[0] = w * v0.x; ac[1] = w * v0.y; ac[2] = w * v0.z; ac[3] = w * v0.w;
        ac[4] = w * v1.x; ac[5] = w * v1.y; ac[6] = w * v1.z; ac[7] = w * v1.w;
    }

    if (cached) {
        __syncwarp();
        #pragma unroll 2
        for (int j = 0; j < n; j++) {
            int src = ssrc[warp][j];
            float4 le = sle[warp][j];
            float leh = (hd == 0) ? le.x : (hd == 1) ? le.y : (hd == 2) ? le.z : le.w;
            float w = __expf(leh - mh);
            den += w;
            const float4* hr = (const float4*)(g_h + (size_t)src * HF) + lane * 2;
            float4 v0 = hr[0], v1 = hr[1];
            ac[0] += w * v0.x; ac[1] += w * v0.y; ac[2] += w * v0.z; ac[3] += w * v0.w;
            ac[4] += w * v1.x; ac[5] += w * v1.y; ac[6] += w * v1.z; ac[7] += w * v1.w;
        }
    } else {
        for (int e = e0; e < e1; e++) {
            int src = g_csr[e];
            float4 s4 = *(const float4*)(g_s + src * NH);
            float sh = (hd == 0) ? s4.x : (hd == 1) ? s4.y : (hd == 2) ? s4.z : s4.w;
            float w = __expf(leaky(sh + ddh) - mh);
            den += w;
            const float4* hr = (const float4*)(g_h + (size_t)src * HF) + lane * 2;
            float4 v0 = hr[0], v1 = hr[1];
            ac[0] += w * v0.x; ac[1] += w * v0.y; ac[2] += w * v0.z; ac[3] += w * v0.w;
            ac[4] += w * v1.x; ac[5] += w * v1.y; ac[6] += w * v1.z; ac[7] += w * v1.w;
        }
    }

    float inv = 1.f / den;
    int c = lane * 8;
    const float4* bp = (const float4*)(bias + c);
    float4 bb0 = bp[0], bb1 = bp[1];
    float4 o0 = make_float4(fmaxf(ac[0] * inv + bb0.x, 0.f), fmaxf(ac[1] * inv + bb0.y, 0.f),
                            fmaxf(ac[2] * inv + bb0.z, 0.f), fmaxf(ac[3] * inv + bb0.w, 0.f));
    float4 o1 = make_float4(fmaxf(ac[4] * inv + bb1.x, 0.f), fmaxf(ac[5] * inv + bb1.y, 0.f),
                            fmaxf(ac[6] * inv + bb1.z, 0.f), fmaxf(ac[7] * inv + bb1.w, 0.f));
    float4* op = (float4*)(xout + (size_t)dst * HF + c);
    op[0] = o0; op[1] = o1;
}

// ---------------- fused per-graph max pool: grid (NGR, 13) ----------------
__global__ void k_poolall() {
    __shared__ float red[4][64];
    int gi = blockIdx.x, seg = blockIdx.y;
    const float* x; int C, gcol0;
    if (seg == 0)      { x = g_n0; C = FD; gcol0 = 0; }
    else if (seg <= 4) { x = g_n1 + (seg - 1) * 64; C = HF; gcol0 = FD + (seg - 1) * 64; }
    else if (seg <= 8) { x = g_n2 + (seg - 5) * 64; C = HF; gcol0 = FD + HF + (seg - 5) * 64; }
    else               { x = g_n3 + (seg - 9) * 64; C = HF; gcol0 = FD + 2 * HF + (seg - 9) * 64; }
    int col = threadIdx.x & 63;
    int rg = threadIdx.x >> 6;
    int i0 = g_gstart[gi], i1 = g_gstart[gi + 1];
    float m = -3.0e38f;
    for (int i = i0 + rg; i < i1; i += 4) m = fmaxf(m, x[(size_t)i * C + col]);
    red[rg][col] = m;
    __syncthreads();
    if (rg == 0) {
        m = fmaxf(fmaxf(red[0][col], red[1][col]), fmaxf(red[2][col], red[3][col]));
        g_g[gi * GCOLS + gcol0 + col] = m;
    }
}

// ---------------- head MLPs ----------------
__global__ void k_latent(const float* __restrict__ W, const float* __restrict__ b) {
    int gi = blockIdx.x;
    int warp = threadIdx.x >> 5, lane = threadIdx.x & 31;
    int j = blockIdx.y * 8 + warp;
    __shared__ float gs[GCOLS];
    for (int i = threadIdx.x; i < GCOLS; i += 256) gs[i] = g_g[gi * GCOLS + i];
    __syncthreads();
    float acc = 0.f;
    for (int k = lane; k < GCOLS; k += 32) acc += gs[k] * W[(size_t)j * GCOLS + k];
    #pragma unroll
    for (int o = 16; o; o >>= 1) acc += __shfl_xor_sync(0xffffffffu, acc, o);
    if (lane == 0) g_lat[gi * LATD + j] = acc + b[j];
}

__global__ void k_head(const float* __restrict__ muW, const float* __restrict__ mub,
                       const float* __restrict__ vW, const float* __restrict__ vb,
                       float* __restrict__ out) {
    int gi = blockIdx.x;
    int warp = threadIdx.x >> 5, lane = threadIdx.x & 31;
    int j = blockIdx.y * 8 + warp;
    __shared__ float ls[LATD];
    for (int i = threadIdx.x; i < LATD; i += 256) ls[i] = g_lat[gi * LATD + i];
    __syncthreads();
    float am = 0.f, av = 0.f;
    for (int k = lane; k < LATD; k += 32) {
        float l = ls[k];
        am += l * muW[(size_t)j * LATD + k];
        av += l * vW[(size_t)j * LATD + k];
    }
    #pragma unroll
    for (int o = 16; o; o >>= 1) {
        am += __shfl_xor_sync(0xffffffffu, am, o);
        av += __shfl_xor_sync(0xffffffffu, av, o);
    }
    if (lane == 0) {
        out[gi * LATD + j] = am + mub[j];
        out[NGR * LATD + gi * LATD + j] = av + vb[j];
    }
}

// ---------------- launch ----------------
extern "C" void kernel_launch(void* const* d_in, const int* in_sizes, int n_in,
                              void* d_out, int out_size) {
    const float* street  = (const float*)d_in[0];
    const float* build   = (const float*)d_in[1];
    const float* smask   = (const float*)d_in[2];
    const float* bmask   = (const float*)d_in[3];
    const int*   ei      = (const int*)d_in[4];
    const int*   batch   = (const int*)d_in[5];
    const float* sW      = (const float*)d_in[6];
    const float* sb      = (const float*)d_in[7];
    const float* bW      = (const float*)d_in[8];
    const float* bb      = (const float*)d_in[9];
    const float* W1      = (const float*)d_in[10];
    const float* as1     = (const float*)d_in[11];
    const float* ad1     = (const float*)d_in[12];
    const float* b1      = (const float*)d_in[13];
    const float* W2      = (const float*)d_in[14];
    const float* as2     = (const float*)d_in[15];
    const float* ad2     = (const float*)d_in[16];
    const float* b2      = (const float*)d_in[17];
    const float* W3      = (const float*)d_in[18];
    const float* as3     = (const float*)d_in[19];
    const float* ad3     = (const float*)d_in[20];
    const float* b3      = (const float*)d_in[21];
    const float* aggW    = (const float*)d_in[22];
    const float* aggb    = (const float*)d_in[23];
    const float* muW     = (const float*)d_in[24];
    const float* mub     = (const float*)d_in[25];
    const float* varW    = (const float*)d_in[26];
    const float* varb    = (const float*)d_in[27];
    float* out = (float*)d_out;

    int E = in_sizes[4] / 2;
    const int GSMEM = 73728;          // gemm dynamic smem
    const int ESMEM = 14272 * 4;      // encode dynamic smem

    static int attr_set = 0;
    if (!attr_set) {
        cudaFuncSetAttribute(k_gemm, cudaFuncAttributeMaxDynamicSharedMemorySize, GSMEM);
        cudaFuncSetAttribute(k_encode2, cudaFuncAttributeMaxDynamicSharedMemorySize, ESMEM);
        attr_set = 1;
    }

    float *n0, *n1, *n2, *n3;
    cudaGetSymbolAddress((void**)&n0, g_n0);
    cudaGetSymbolAddress((void**)&n1, g_n1);
    cudaGetSymbolAddress((void**)&n2, g_n2);
    cudaGetSymbolAddress((void**)&n3, g_n3);

    // 0: encode (tf32 mma) + hist + counter reset
    k_encode2<<<ENCB, 256, ESMEM>>>(street, build, smask, bmask,
                                    sW, sb, bW, bb, ei, E);
    // 1: scan + scatter + gbounds + deg reset
    k_scan<<<NBLK, 256>>>(ei, batch, E);
    // 2: layer-1 GEMM
    k_gemm<<<GEMMB, 256, GSMEM>>>(n0, W1, FD, as1, ad1);
    // 3: agg L1 (PROFILED LAUNCH)
    k_agg<<<(NN + 7) / 8, 256>>>(b1, n1);
    // 4-5: layer 2
    k_gemm<<<GEMMB, 256, GSMEM>>>(n1, W2, HF, as2, ad2);
    k_agg<<<(NN + 7) / 8, 256>>>(b2, n2);
    // 6-7: layer 3
    k_gemm<<<GEMMB, 256, GSMEM>>>(n2, W3, HF, as3, ad3);
    k_agg<<<(NN + 7) / 8, 256>>>(b3, n3);
    // 8: fused pooling
    k_poolall<<<dim3(NGR, 13), 256>>>();
    // 9-10: head
    k_latent<<<dim3(NGR, LATD / 8), 256>>>(aggW, aggb);
    k_head<<<dim3(NGR, LATD / 8), 256>>>(muW, mub, varW, varb, out);
}

// round 8
// speedup vs baseline: 4.4645x; 1.2092x over previous
#include <cuda_runtime.h>
#include <math.h>
#include <stdint.h>

#define NN 20000
#define NE 320000
#define FD 64
#define NH 4
#define HF 256    // NH*FD
#define NGR 64
#define LATD 512
#define GCOLS 832  // FD*(1+3*NH)
#define NBLK ((NN + 255) / 256)   // 79 scan blocks (all co-resident)
#define GEMMB 314 // gemm blocks: ceil(20000/128)*2
#define ENCB 157  // encode blocks: ceil(20000/128)
#define CAP 64    // cached edges per dst in k_agg

// ---------------- scratch (static device globals; no allocs) ----------------
__device__ float g_n0[NN * FD];
__device__ float g_n1[NN * HF];
__device__ float g_n2[NN * HF];
__device__ float g_n3[NN * HF];
__device__ float g_h [NN * HF];
__device__ float g_s [NN * NH];
__device__ float g_d [NN * NH];
__device__ int   g_deg[NN + 1];
__device__ int   g_off[NN + 1];
__device__ int   g_cur[NN];
__device__ int   g_csr[NE];
__device__ int   g_bsum[NBLK + 1];
__device__ int   g_ctrA;
__device__ int   g_ctrB;
__device__ int   g_gstart[NGR + 1];
__device__ float g_g[NGR * GCOLS];
__device__ float g_lat[NGR * LATD];

__device__ __forceinline__ float leaky(float x) { return x > 0.f ? x : 0.2f * x; }

__device__ __forceinline__ void cpa16(uint32_t dst, const void* src, bool p) {
    asm volatile("cp.async.ca.shared.global [%0], [%1], 16, %2;"
                 :: "r"(dst), "l"(src), "r"(p ? 16 : 0));
}

// ---------------- encode via tf32 mma + edge histogram + counter reset ----------------
__global__ void __launch_bounds__(256) k_encode2(
        const float* __restrict__ sf, const float* __restrict__ bfeat,
        const float* __restrict__ smk, const float* __restrict__ bmk,
        const float* __restrict__ sW, const float* __restrict__ sb,
        const float* __restrict__ bW, const float* __restrict__ bb,
        const int* __restrict__ ei, int E) {
    extern __shared__ float smem[];
    float* sbs = smem + 13824;
    float* bbs = smem + 13888;
    float* bWs = smem + 13952;
    int tid = threadIdx.x;
    int lane = tid & 31, warp = tid >> 5;
    int warpM = warp >> 1, warpN = warp & 1;
    int bm = blockIdx.x * 128;
    int gid = lane >> 2, tig = lane & 3;
    uint32_t smb = (uint32_t)__cvta_generic_to_shared(smem);

    if (blockIdx.x == 0 && tid == 0) { g_ctrA = 0; g_ctrB = 0; }

    for (int i = blockIdx.x * 256 + tid; i < E; i += ENCB * 256)
        atomicAdd(&g_deg[ei[E + i]], 1);

    if (tid < 64) { sbs[tid] = sb[tid]; bbs[tid] = bb[tid]; }
    for (int l = tid; l < 320; l += 256) bWs[l] = bW[l];

    float acc[2][4][4];
    #pragma unroll
    for (int mt = 0; mt < 2; mt++)
        #pragma unroll
        for (int nt = 0; nt < 4; nt++)
            #pragma unroll
            for (int j = 0; j < 4; j++) acc[mt][nt][j] = 0.f;

    #define ECOPY(ii, ss) do {                                                   \
        int k0_ = (ii) * 32;                                                     \
        _Pragma("unroll")                                                        \
        for (int l = 0; l < 4; l++) {                                            \
            int idx = tid + 256 * l;                                             \
            int row = idx >> 3, k4 = idx & 7;                                    \
            int gr = bm + row;                                                   \
            bool p = gr < NN;                                                    \
            int grc = p ? gr : (NN - 1);                                         \
            cpa16(smb + ((ss) * 4608 + row * 36 + k4 * 4) * 4,                   \
                  sf + (size_t)grc * 128 + k0_ + k4 * 4, p);                     \
        }                                                                        \
        _Pragma("unroll")                                                        \
        for (int l = 0; l < 2; l++) {                                            \
            int idx = tid + 256 * l;                                             \
            int row = idx >> 3, k4 = idx & 7;                                    \
            cpa16(smb + (9216 + (ss) * 2304 + row * 36 + k4 * 4) * 4,            \
                  sW + (size_t)row * 128 + k0_ + k4 * 4, true);                  \
        }                                                                        \
        asm volatile("cp.async.commit_group;");                                  \
    } while (0)

    ECOPY(0, 0);
    for (int i = 0; i < 4; i++) {
        asm volatile("cp.async.wait_group 0;");
        __syncthreads();
        if (i + 1 < 4) ECOPY(i + 1, (i + 1) & 1);
        const float* As_ = smem + (i & 1) * 4608;
        const float* Bs_ = smem + 9216 + (i & 1) * 2304;
        #pragma unroll
        for (int k8 = 0; k8 < 4; k8++) {
            unsigned a[2][4];
            int col = k8 * 8 + tig;
            #pragma unroll
            for (int mt = 0; mt < 2; mt++) {
                int row = warpM * 32 + mt * 16 + gid;
                a[mt][0] = __float_as_uint(As_[row * 36 + col]);
                a[mt][1] = __float_as_uint(As_[(row + 8) * 36 + col]);
                a[mt][2] = __float_as_uint(As_[row * 36 + col + 4]);
                a[mt][3] = __float_as_uint(As_[(row + 8) * 36 + col + 4]);
            }
            #pragma unroll
            for (int nt = 0; nt < 4; nt++) {
                int colB = warpN * 32 + nt * 8 + gid;
                int rowB = k8 * 8 + tig;
                unsigned b0 = __float_as_uint(Bs_[colB * 36 + rowB]);
                unsigned b1 = __float_as_uint(Bs_[colB * 36 + rowB + 4]);
                #pragma unroll
                for (int mt = 0; mt < 2; mt++) {
                    asm volatile(
                        "mma.sync.aligned.m16n8k8.row.col.f32.tf32.tf32.f32 "
                        "{%0,%1,%2,%3}, {%4,%5,%6,%7}, {%8,%9}, {%0,%1,%2,%3};"
                        : "+f"(acc[mt][nt][0]), "+f"(acc[mt][nt][1]),
                          "+f"(acc[mt][nt][2]), "+f"(acc[mt][nt][3])
                        : "r"(a[mt][0]), "r"(a[mt][1]), "r"(a[mt][2]), "r"(a[mt][3]),
                          "r"(b0), "r"(b1));
                }
            }
        }
        __syncthreads();
    }
    #undef ECOPY

    #pragma unroll
    for (int mt = 0; mt < 2; mt++) {
        int row0 = bm + warpM * 32 + mt * 16 + gid;
        int r1 = row0 + 8;
        int rc0 = (row0 < NN) ? row0 : (NN - 1);
        int rc1 = (r1 < NN) ? r1 : (NN - 1);
        float bf0[5], bf1[5];
        #pragma unroll
        for (int i = 0; i < 5; i++) { bf0[i] = bfeat[rc0 * 5 + i]; bf1[i] = bfeat[rc1 * 5 + i]; }
        float sm0 = smk[rc0], bm0 = bmk[rc0], sm1 = smk[rc1], bm1 = bmk[rc1];
        #pragma unroll
        for (int nt = 0; nt < 4; nt++) {
            int col = warpN * 32 + nt * 8 + tig * 2;
            float o0[2], o1[2];
            #pragma unroll
            for (int c = 0; c < 2; c++) {
                int f = col + c;
                float aS0 = fmaxf(acc[mt][nt][c] + sbs[f], 0.f);
                float aS1 = fmaxf(acc[mt][nt][2 + c] + sbs[f], 0.f);
                float aB0 = bbs[f], aB1 = bbs[f];
                #pragma unroll
                for (int i = 0; i < 5; i++) {
                    aB0 += bf0[i] * bWs[f * 5 + i];
                    aB1 += bf1[i] * bWs[f * 5 + i];
                }
                aB0 = fmaxf(aB0, 0.f); aB1 = fmaxf(aB1, 0.f);
                o0[c] = aS0 * sm0 + aB0 * bm0;
                o1[c] = aS1 * sm1 + aB1 * bm1;
            }
            if (row0 < NN) *(float2*)(g_n0 + (size_t)row0 * FD + col) = make_float2(o0[0], o0[1]);
            if (r1 < NN)   *(float2*)(g_n0 + (size_t)r1 * FD + col)   = make_float2(o1[0], o1[1]);
        }
    }
}

// ---------------- grid barrier for k_scan (79 co-resident blocks) ----------------
__device__ __forceinline__ void gbarrier(int* ctr) {
    __threadfence();
    __syncthreads();
    if (threadIdx.x == 0) {
        atomicAdd(ctr, 1);
        while (atomicAdd(ctr, 0) < NBLK) __nanosleep(32);
        __threadfence();
    }
    __syncthreads();
}

// ---------------- scan + scatter + gbounds + deg reset (single kernel) ----------------
__global__ void __launch_bounds__(256) k_scan(const int* __restrict__ ei,
                                              const int* __restrict__ batch, int E) {
    __shared__ int wsum[8];
    __shared__ int pre_s;
    int b = blockIdx.x, tid = threadIdx.x, lane = tid & 31, w = tid >> 5;
    int i = b * 256 + tid;
    int v = (i < NN) ? g_deg[i] : 0;
    int x = v;
    #pragma unroll
    for (int o = 1; o < 32; o <<= 1) {
        int y = __shfl_up_sync(0xffffffffu, x, o);
        if (lane >= o) x += y;
    }
    if (lane == 31) wsum[w] = x;
    __syncthreads();
    if (tid < 8) {
        int t2 = wsum[tid];
        #pragma unroll
        for (int o = 1; o < 8; o <<= 1) {
            int y = __shfl_up_sync(0xffu, t2, o);
            if (tid >= o) t2 += y;
        }
        wsum[tid] = t2;
    }
    __syncthreads();
    int excl = x - v + (w > 0 ? wsum[w - 1] : 0);
    if (tid == 255) g_bsum[b] = excl + v;

    gbarrier(&g_ctrA);

    if (tid < 32) {
        int s = 0;
        for (int j = tid; j < b; j += 32) s += g_bsum[j];
        #pragma unroll
        for (int o = 16; o; o >>= 1) s += __shfl_xor_sync(0xffffffffu, s, o);
        if (tid == 0) pre_s = s;
    }
    __syncthreads();
    if (i < NN) {
        int o = excl + pre_s;
        g_off[i] = o;
        g_cur[i] = o;
        g_deg[i] = 0;
    }
    if (i == 0) { g_off[NN] = E; g_gstart[0] = 0; g_gstart[NGR] = NN; }

    gbarrier(&g_ctrB);

    for (int e = b * 256 + tid; e < E; e += NBLK * 256) {
        int dd = ei[E + e];
        int p = atomicAdd(&g_cur[dd], 1);
        g_csr[p] = ei[e];
    }
    for (int j = b * 256 + tid; j < NN; j += NBLK * 256) {
        if (j > 0 && batch[j] != batch[j - 1]) g_gstart[batch[j]] = j;
    }
}

// ---------------- tf32 mma GEMM (cp.async 2-stage) + fused s/d logits ----------------
__global__ void __launch_bounds__(256, 2) k_gemm(const float* __restrict__ A,
        const float* __restrict__ W, int Kdim,
        const float* __restrict__ as_, const float* __restrict__ ad_) {
    extern __shared__ float smemf[];
    int tid = threadIdx.x;
    int lane = tid & 31, warp = tid >> 5;
    int warpM = warp >> 1, warpN = warp & 1;
    int mi = blockIdx.x >> 1, ni = blockIdx.x & 1;
    int bm = mi * 128, bn = ni * 128;
    int gid = lane >> 2, tig = lane & 3;
    uint32_t smb = (uint32_t)__cvta_generic_to_shared(smemf);

    float acc[2][8][4];
    #pragma unroll
    for (int mt = 0; mt < 2; mt++)
        #pragma unroll
        for (int nt = 0; nt < 8; nt++)
            #pragma unroll
            for (int j = 0; j < 4; j++) acc[mt][nt][j] = 0.f;

    int nk = Kdim >> 5;

    #define COPY_STAGE(ii, ss) do {                                              \
        int k0_ = (ii) * 32;                                                     \
        _Pragma("unroll")                                                        \
        for (int l = 0; l < 4; l++) {                                            \
            int idx = tid + 256 * l;                                             \
            int row = idx >> 3, k4 = idx & 7;                                    \
            int gr = bm + row;                                                   \
            bool p = gr < NN;                                                    \
            int grc = p ? gr : (NN - 1);                                         \
            cpa16(smb + ((ss) * 4608 + row * 36 + k4 * 4) * 4,                   \
                  A + (size_t)grc * Kdim + k0_ + k4 * 4, p);                     \
            cpa16(smb + (9216 + (ss) * 4608 + row * 36 + k4 * 4) * 4,            \
                  W + (size_t)(bn + row) * Kdim + k0_ + k4 * 4, true);           \
        }                                                                        \
        asm volatile("cp.async.commit_group;");                                  \
    } while (0)

    COPY_STAGE(0, 0);

    for (int i = 0; i < nk; i++) {
        asm volatile("cp.async.wait_group 0;");
        __syncthreads();
        if (i + 1 < nk) COPY_STAGE(i + 1, (i + 1) & 1);

        const float* As_ = smemf + (i & 1) * 4608;
        const float* Bs_ = smemf + 9216 + (i & 1) * 4608;
        #pragma unroll
        for (int k8 = 0; k8 < 4; k8++) {
            unsigned a[2][4];
            int col = k8 * 8 + tig;
            #pragma unroll
            for (int mt = 0; mt < 2; mt++) {
                int row = warpM * 32 + mt * 16 + gid;
                a[mt][0] = __float_as_uint(As_[row * 36 + col]);
                a[mt][1] = __float_as_uint(As_[(row + 8) * 36 + col]);
                a[mt][2] = __float_as_uint(As_[row * 36 + col + 4]);
                a[mt][3] = __float_as_uint(As_[(row + 8) * 36 + col + 4]);
            }
            #pragma unroll
            for (int nt = 0; nt < 8; nt++) {
                int colB = warpN * 64 + nt * 8 + gid;
                int rowB = k8 * 8 + tig;
                unsigned b0 = __float_as_uint(Bs_[colB * 36 + rowB]);
                unsigned b1 = __float_as_uint(Bs_[colB * 36 + rowB + 4]);
                #pragma unroll
                for (int mt = 0; mt < 2; mt++) {
                    asm volatile(
                        "mma.sync.aligned.m16n8k8.row.col.f32.tf32.tf32.f32 "
                        "{%0,%1,%2,%3}, {%4,%5,%6,%7}, {%8,%9}, {%0,%1,%2,%3};"
                        : "+f"(acc[mt][nt][0]), "+f"(acc[mt][nt][1]),
                          "+f"(acc[mt][nt][2]), "+f"(acc[mt][nt][3])
                        : "r"(a[mt][0]), "r"(a[mt][1]), "r"(a[mt][2]), "r"(a[mt][3]),
                          "r"(b0), "r"(b1));
                }
            }
        }
    }
    #undef COPY_STAGE
    __syncthreads();

    int hd = (bn >> 6) + warpN;
    #pragma unroll
    for (int mt = 0; mt < 2; mt++) {
        int row0 = bm + warpM * 32 + mt * 16 + gid;
        float sp0 = 0.f, sp8 = 0.f, dp0 = 0.f, dp8 = 0.f;
        #pragma unroll
        for (int nt = 0; nt < 8; nt++) {
            int col = bn + warpN * 64 + nt * 8 + tig * 2;
            int lc = nt * 8 + tig * 2;
            float2 a2s = *(const float2*)(as_ + hd * 64 + lc);
            float2 a2d = *(const float2*)(ad_ + hd * 64 + lc);
            sp0 += acc[mt][nt][0] * a2s.x + acc[mt][nt][1] * a2s.y;
            sp8 += acc[mt][nt][2] * a2s.x + acc[mt][nt][3] * a2s.y;
            dp0 += acc[mt][nt][0] * a2d.x + acc[mt][nt][1] * a2d.y;
            dp8 += acc[mt][nt][2] * a2d.x + acc[mt][nt][3] * a2d.y;
            if (row0 < NN)
                *(float2*)(g_h + (size_t)row0 * HF + col) =
                    make_float2(acc[mt][nt][0], acc[mt][nt][1]);
            if (row0 + 8 < NN)
                *(float2*)(g_h + (size_t)(row0 + 8) * HF + col) =
                    make_float2(acc[mt][nt][2], acc[mt][nt][3]);
        }
        #pragma unroll
        for (int o = 1; o < 4; o <<= 1) {
            sp0 += __shfl_xor_sync(0xffffffffu, sp0, o);
            sp8 += __shfl_xor_sync(0xffffffffu, sp8, o);
            dp0 += __shfl_xor_sync(0xffffffffu, dp0, o);
            dp8 += __shfl_xor_sync(0xffffffffu, dp8, o);
        }
        if (tig == 0) {
            if (row0 < NN)     { g_s[row0 * NH + hd] = sp0; g_d[row0 * NH + hd] = dp0; }
            if (row0 + 8 < NN) { g_s[(row0 + 8) * NH + hd] = sp8; g_d[(row0 + 8) * NH + hd] = dp8; }
        }
    }
}

// ---------------- GAT aggregation: warp per dst, COALESCED feature loads
// lane l owns float4 #l (feats 4l..4l+3, head lane/16) and float4 #(32+l)
// (feats 128+4l.., head 2+lane/16). Each LDG.128 touches 4 lines (coalesced).
__global__ void __launch_bounds__(256, 4) k_agg(const float* __restrict__ bias,
                                                float* __restrict__ xout) {
    __shared__ float4 sle[8][CAP + 1];
    __shared__ int    ssrc[8][CAP + 1];
    int warp = threadIdx.x >> 5, lane = threadIdx.x & 31;
    int dst = blockIdx.x * 8 + warp;
    if (dst >= NN) return;
    int e0 = g_off[dst], e1 = g_off[dst + 1];
    int n = e1 - e0;
    bool cached = (n <= CAP);
    float4 d4 = *(const float4*)(g_d + dst * NH);
    float4 s4self = *(const float4*)(g_s + dst * NH);

    // pass 1: per-head max + cache (src, leaky logits)
    float4 m;
    m.x = leaky(s4self.x + d4.x); m.y = leaky(s4self.y + d4.y);
    m.z = leaky(s4self.z + d4.z); m.w = leaky(s4self.w + d4.w);
    for (int j = lane; j < n; j += 32) {
        int src = g_csr[e0 + j];
        float4 s4 = *(const float4*)(g_s + src * NH);
        float4 le = make_float4(leaky(s4.x + d4.x), leaky(s4.y + d4.y),
                                leaky(s4.z + d4.z), leaky(s4.w + d4.w));
        m.x = fmaxf(m.x, le.x); m.y = fmaxf(m.y, le.y);
        m.z = fmaxf(m.z, le.z); m.w = fmaxf(m.w, le.w);
        if (cached) { ssrc[warp][j] = src; sle[warp][j] = le; }
    }
    #pragma unroll
    for (int o = 16; o; o >>= 1) {
        m.x = fmaxf(m.x, __shfl_xor_sync(0xffffffffu, m.x, o));
        m.y = fmaxf(m.y, __shfl_xor_sync(0xffffffffu, m.y, o));
        m.z = fmaxf(m.z, __shfl_xor_sync(0xffffffffu, m.z, o));
        m.w = fmaxf(m.w, __shfl_xor_sync(0xffffffffu, m.w, o));
    }

    bool hi = lane >= 16;
    float mA = hi ? m.y : m.x;                      // head h1 = lane/16
    float mB = hi ? m.w : m.z;                      // head h2 = 2 + lane/16
    float leselfA = hi ? leaky(s4self.y + d4.y) : leaky(s4self.x + d4.x);
    float leselfB = hi ? leaky(s4self.w + d4.w) : leaky(s4self.z + d4.z);
    float ddA = hi ? d4.y : d4.x;
    float ddB = hi ? d4.w : d4.z;

    // self contribution (coalesced: float4 #lane, #32+lane)
    float denA, denB;
    float4 acA, acB;
    {
        float wA = __expf(leselfA - mA);
        float wB = __expf(leselfB - mB);
        denA = wA; denB = wB;
        const float4* hr = (const float4*)(g_h + (size_t)dst * HF);
        float4 vA = hr[lane], vB = hr[32 + lane];
        acA = make_float4(wA * vA.x, wA * vA.y, wA * vA.z, wA * vA.w);
        acB = make_float4(wB * vB.x, wB * vB.y, wB * vB.z, wB * vB.w);
    }

    if (cached) {
        __syncwarp();
        #pragma unroll 2
        for (int j = 0; j < n; j++) {
            int src = ssrc[warp][j];
            float4 le = sle[warp][j];
            float leA = hi ? le.y : le.x;
            float leB = hi ? le.w : le.z;
            float wA = __expf(leA - mA);
            float wB = __expf(leB - mB);
            const float4* hr = (const float4*)(g_h + (size_t)src * HF);
            float4 vA = hr[lane], vB = hr[32 + lane];
            denA += wA; denB += wB;
            acA.x += wA * vA.x; acA.y += wA * vA.y; acA.z += wA * vA.z; acA.w += wA * vA.w;
            acB.x += wB * vB.x; acB.y += wB * vB.y; acB.z += wB * vB.z; acB.w += wB * vB.w;
        }
    } else {
        for (int e = e0; e < e1; e++) {
            int src = g_csr[e];
            float4 s4 = *(const float4*)(g_s + src * NH);
            float leA = leaky((hi ? s4.y : s4.x) + ddA);
            float leB = leaky((hi ? s4.w : s4.z) + ddB);
            float wA = __expf(leA - mA);
            float wB = __expf(leB - mB);
            const float4* hr = (const float4*)(g_h + (size_t)src * HF);
            float4 vA = hr[lane], vB = hr[32 + lane];
            denA += wA; denB += wB;
            acA.x += wA * vA.x; acA.y += wA * vA.y; acA.z += wA * vA.z; acA.w += wA * vA.w;
            acB.x += wB * vB.x; acB.y += wB * vB.y; acB.z += wB * vB.z; acB.w += wB * vB.w;
        }
    }

    float invA = 1.f / denA, invB = 1.f / denB;
    const float4* bp = (const float4*)bias;
    float4 bA = bp[lane], bB = bp[32 + lane];
    float4 oA = make_float4(fmaxf(acA.x * invA + bA.x, 0.f), fmaxf(acA.y * invA + bA.y, 0.f),
                            fmaxf(acA.z * invA + bA.z, 0.f), fmaxf(acA.w * invA + bA.w, 0.f));
    float4 oB = make_float4(fmaxf(acB.x * invB + bB.x, 0.f), fmaxf(acB.y * invB + bB.y, 0.f),
                            fmaxf(acB.z * invB + bB.z, 0.f), fmaxf(acB.w * invB + bB.w, 0.f));
    float4* op = (float4*)(xout + (size_t)dst * HF);
    op[lane] = oA;
    op[32 + lane] = oB;
}

// ---------------- fused per-graph max pool: grid (NGR, 13) ----------------
__global__ void k_poolall() {
    __shared__ float red[4][64];
    int gi = blockIdx.x, seg = blockIdx.y;
    const float* x; int C, gcol0;
    if (seg == 0)      { x = g_n0; C = FD; gcol0 = 0; }
    else if (seg <= 4) { x = g_n1 + (seg - 1) * 64; C = HF; gcol0 = FD + (seg - 1) * 64; }
    else if (seg <= 8) { x = g_n2 + (seg - 5) * 64; C = HF; gcol0 = FD + HF + (seg - 5) * 64; }
    else               { x = g_n3 + (seg - 9) * 64; C = HF; gcol0 = FD + 2 * HF + (seg - 9) * 64; }
    int col = threadIdx.x & 63;
    int rg = threadIdx.x >> 6;
    int i0 = g_gstart[gi], i1 = g_gstart[gi + 1];
    float m = -3.0e38f;
    for (int i = i0 + rg; i < i1; i += 4) m = fmaxf(m, x[(size_t)i * C + col]);
    red[rg][col] = m;
    __syncthreads();
    if (rg == 0) {
        m = fmaxf(fmaxf(red[0][col], red[1][col]), fmaxf(red[2][col], red[3][col]));
        g_g[gi * GCOLS + gcol0 + col] = m;
    }
}

// ---------------- head MLPs ----------------
__global__ void k_latent(const float* __restrict__ W, const float* __restrict__ b) {
    int gi = blockIdx.x;
    int warp = threadIdx.x >> 5, lane = threadIdx.x & 31;
    int j = blockIdx.y * 8 + warp;
    __shared__ float gs[GCOLS];
    for (int i = threadIdx.x; i < GCOLS; i += 256) gs[i] = g_g[gi * GCOLS + i];
    __syncthreads();
    float acc = 0.f;
    for (int k = lane; k < GCOLS; k += 32) acc += gs[k] * W[(size_t)j * GCOLS + k];
    #pragma unroll
    for (int o = 16; o; o >>= 1) acc += __shfl_xor_sync(0xffffffffu, acc, o);
    if (lane == 0) g_lat[gi * LATD + j] = acc + b[j];
}

__global__ void k_head(const float* __restrict__ muW, const float* __restrict__ mub,
                       const float* __restrict__ vW, const float* __restrict__ vb,
                       float* __restrict__ out) {
    int gi = blockIdx.x;
    int warp = threadIdx.x >> 5, lane = threadIdx.x & 31;
    int j = blockIdx.y * 8 + warp;
    __shared__ float ls[LATD];
    for (int i = threadIdx.x; i < LATD; i += 256) ls[i] = g_lat[gi * LATD + i];
    __syncthreads();
    float am = 0.f, av = 0.f;
    for (int k = lane; k < LATD; k += 32) {
        float l = ls[k];
        am += l * muW[(size_t)j * LATD + k];
        av += l * vW[(size_t)j * LATD + k];
    }
    #pragma unroll
    for (int o = 16; o; o >>= 1) {
        am += __shfl_xor_sync(0xffffffffu, am, o);
        av += __shfl_xor_sync(0xffffffffu, av, o);
    }
    if (lane == 0) {
        out[gi * LATD + j] = am + mub[j];
        out[NGR * LATD + gi * LATD + j] = av + vb[j];
    }
}

// ---------------- launch ----------------
extern "C" void kernel_launch(void* const* d_in, const int* in_sizes, int n_in,
                              void* d_out, int out_size) {
    const float* street  = (const float*)d_in[0];
    const float* build   = (const float*)d_in[1];
    const float* smask   = (const float*)d_in[2];
    const float* bmask   = (const float*)d_in[3];
    const int*   ei      = (const int*)d_in[4];
    const int*   batch   = (const int*)d_in[5];
    const float* sW      = (const float*)d_in[6];
    const float* sb      = (const float*)d_in[7];
    const float* bW      = (const float*)d_in[8];
    const float* bb      = (const float*)d_in[9];
    const float* W1      = (const float*)d_in[10];
    const float* as1     = (const float*)d_in[11];
    const float* ad1     = (const float*)d_in[12];
    const float* b1      = (const float*)d_in[13];
    const float* W2      = (const float*)d_in[14];
    const float* as2     = (const float*)d_in[15];
    const float* ad2     = (const float*)d_in[16];
    const float* b2      = (const float*)d_in[17];
    const float* W3      = (const float*)d_in[18];
    const float* as3     = (const float*)d_in[19];
    const float* ad3     = (const float*)d_in[20];
    const float* b3      = (const float*)d_in[21];
    const float* aggW    = (const float*)d_in[22];
    const float* aggb    = (const float*)d_in[23];
    const float* muW     = (const float*)d_in[24];
    const float* mub     = (const float*)d_in[25];
    const float* varW    = (const float*)d_in[26];
    const float* varb    = (const float*)d_in[27];
    float* out = (float*)d_out;

    int E = in_sizes[4] / 2;
    const int GSMEM = 73728;
    const int ESMEM = 14272 * 4;

    static int attr_set = 0;
    if (!attr_set) {
        cudaFuncSetAttribute(k_gemm, cudaFuncAttributeMaxDynamicSharedMemorySize, GSMEM);
        cudaFuncSetAttribute(k_encode2, cudaFuncAttributeMaxDynamicSharedMemorySize, ESMEM);
        attr_set = 1;
    }

    float *n0, *n1, *n2, *n3;
    cudaGetSymbolAddress((void**)&n0, g_n0);
    cudaGetSymbolAddress((void**)&n1, g_n1);
    cudaGetSymbolAddress((void**)&n2, g_n2);
    cudaGetSymbolAddress((void**)&n3, g_n3);

    // 0: encode (tf32 mma) + hist + counter reset
    k_encode2<<<ENCB, 256, ESMEM>>>(street, build, smask, bmask,
                                    sW, sb, bW, bb, ei, E);
    // 1: scan + scatter + gbounds + deg reset
    k_scan<<<NBLK, 256>>>(ei, batch, E);
    // 2: layer-1 GEMM
    k_gemm<<<GEMMB, 256, GSMEM>>>(n0, W1, FD, as1, ad1);
    // 3: agg L1 (PROFILED LAUNCH)
    k_agg<<<(NN + 7) / 8, 256>>>(b1, n1);
    // 4-5: layer 2
    k_gemm<<<GEMMB, 256, GSMEM>>>(n1, W2, HF, as2, ad2);
    k_agg<<<(NN + 7) / 8, 256>>>(b2, n2);
    // 6-7: layer 3
    k_gemm<<<GEMMB, 256, GSMEM>>>(n2, W3, HF, as3, ad3);
    k_agg<<<(NN + 7) / 8, 256>>>(b3, n3);
    // 8: fused pooling
    k_poolall<<<dim3(NGR, 13), 256>>>();
    // 9-10: head
    k_latent<<<dim3(NGR, LATD / 8), 256>>>(aggW, aggb);
    k_head<<<dim3(NGR, LATD / 8), 256>>>(muW, mub, varW, varb, out);
}